// round 10
// baseline (speedup 1.0000x reference)
#include <cuda_runtime.h>
#include <cuda_bf16.h>
#include <stdint.h>

// ============================================================================
// LightAttention via mma.sync m16n8k8 TF32. 128x128 CTA tiles, 2 CTAs/SM,
// 2-stage cp.async pipelines. s8 sub-loop kept rolled (#pragma unroll 1) so
// warps de-phase within a chunk and cover each other's LDSM latency.
//   projkv:  eKT[d,n]=exp((xk@Wk+b)^T*s) (+row sums) ; VT[e,n]=(xv@Wv+b)^T
//   projq_bm (merged): first 1024 CTAs: eQ[n,d]=exp((xq@Wq+b)*s) (+col sums);
//                      last 512 CTAs: bm_split split-K x4 (needs only eKT/VT)
//   combine_sums; bm_combine (sum+1/(ks*qs)+round); z_gemm: Z = eQ @ BmT^T.
// W and intermediates RNE-rounded to tf32; x enters raw fp32 (mma truncation
// unbiased vs zero-mean W). Softmax max dropped (exp args in [-0.75,0.75]).
// ============================================================================

#define B_SZ   8
#define N_SEQ  4096
#define DM     512
#define M_ALL  (B_SZ * N_SEQ)
#define ELTS   ((size_t)M_ALL * DM)

static __device__ __constant__ float kINVS = 0.21022410381342863f; // 512^-0.25

// ---------------- scratch ----------------
__device__ __align__(16) float g_Wt[3 * DM * DM];
__device__ __align__(16) float g_eQ[ELTS];
__device__ __align__(16) float g_eKT[ELTS];
__device__ __align__(16) float g_VT[ELTS];
__device__ __align__(16) float g_BmT[B_SZ * DM * DM];
__device__ __align__(16) float g_BmP[4 * B_SZ * DM * DM];
__device__ float g_pq[256 * DM];
__device__ float g_pk[256 * DM];
__device__ float g_sum[2 * B_SZ * DM];

// ---------------- helpers ----------------
__device__ __forceinline__ uint32_t smem_u32(const void* p) {
    uint32_t r;
    asm("{ .reg .u64 t; cvta.to.shared.u64 t, %1; cvt.u32.u64 %0, t; }" : "=r"(r) : "l"(p));
    return r;
}
// RNE round fp32 -> tf32
__device__ __forceinline__ float rtf(float x) {
    uint32_t u = __float_as_uint(x);
    u = (u + 0x00000FFFu + ((u >> 13) & 1u)) & 0xFFFFE000u;
    return __uint_as_float(u);
}
__device__ __forceinline__ void ldmx4(uint32_t r[4], uint32_t addr) {
    asm volatile("ldmatrix.sync.aligned.m8n8.x4.shared.b16 {%0,%1,%2,%3}, [%4];"
                 : "=r"(r[0]), "=r"(r[1]), "=r"(r[2]), "=r"(r[3]) : "r"(addr));
}
__device__ __forceinline__ void mmatf32(float c[4], const uint32_t a[4],
                                        uint32_t b0, uint32_t b1) {
    asm volatile("mma.sync.aligned.m16n8k8.row.col.f32.tf32.tf32.f32 "
                 "{%0,%1,%2,%3}, {%4,%5,%6,%7}, {%8,%9}, {%0,%1,%2,%3};"
                 : "+f"(c[0]), "+f"(c[1]), "+f"(c[2]), "+f"(c[3])
                 : "r"(a[0]), "r"(a[1]), "r"(a[2]), "r"(a[3]), "r"(b0), "r"(b1));
}

#define PITCH    144            // 32 fp32 (128B) + 16B pad
#define MATB     18432          // 128 * 144
#define STAGE_B  36864          // 2 matrices
#define SMEM_BYTES 73728        // 2 stages
#define SPB2     528
#define SW_OFF   67584

// k32 chunk: A[128,32] @ B[128,32]^T, warp 64x32. s8 loop intentionally
// rolled: per step [6 LDSM -> 16 HMMA] so concurrent warps de-phase and the
// tensor pipe stays fed during other warps' LDSM heads.
__device__ __forceinline__ void gemm_tf32(uint32_t aBase, uint32_t bBase,
                                          int wm, int wn, int lane, float acc[4][4][4]) {
    const int arow = wm * 64 + (lane & 15);
    const int brow = wn * 32 + (lane & 15);
    const uint32_t lhi = (uint32_t)((lane >> 4) * 16);
#pragma unroll 1
    for (int s8 = 0; s8 < 4; ++s8) {
        const uint32_t kb = (uint32_t)(s8 * 32) + lhi;
        uint32_t a[4][4], b[2][4];
#pragma unroll
        for (int ng = 0; ng < 2; ++ng)
            ldmx4(b[ng], bBase + (uint32_t)(brow + ng * 16) * PITCH + kb);
#pragma unroll
        for (int mt = 0; mt < 4; ++mt)
            ldmx4(a[mt], aBase + (uint32_t)(arow + mt * 16) * PITCH + kb);
#pragma unroll
        for (int mt = 0; mt < 4; ++mt)
#pragma unroll
            for (int nt = 0; nt < 4; ++nt)
                mmatf32(acc[mt][nt], a[mt], b[nt >> 1][nt & 1], b[nt >> 1][(nt & 1) + 2]);
    }
}

// ---------------- async stage loader (2 matrices) ----------------
__device__ __forceinline__ void load2(uint32_t smbase, int s,
                                      const float* aP, int as,
                                      const float* bP, int bs, int kc, int tid) {
    const uint32_t base = smbase + s * STAGE_B;
#pragma unroll
    for (int i = 0; i < 4; ++i) {
        const int idx = tid + i * 256, row = idx >> 3, c16 = idx & 7;
        const uint32_t d = base + row * PITCH + c16 * 16;
        const float* g = aP + (size_t)row * as + kc + c16 * 4;
        asm volatile("cp.async.cg.shared.global [%0], [%1], 16;" :: "r"(d), "l"(g));
    }
#pragma unroll
    for (int i = 0; i < 4; ++i) {
        const int idx = tid + i * 256, row = idx >> 3, c16 = idx & 7;
        const uint32_t d = base + MATB + row * PITCH + c16 * 16;
        const float* g = bP + (size_t)row * bs + kc + c16 * 4;
        asm volatile("cp.async.cg.shared.global [%0], [%1], 16;" :: "r"(d), "l"(g));
    }
    asm volatile("cp.async.commit_group;");
}

// 2-stage mainloop over NCH chunks of K=32 starting at k0.
template<int NCH>
__device__ __forceinline__ void mainloop2(uint32_t smbase,
                                          const float* aP, int as,
                                          const float* bP, int bs, int k0,
                                          int tid, int wm, int wn, int lane,
                                          float acc[4][4][4]) {
    load2(smbase, 0, aP, as, bP, bs, k0, tid);
#pragma unroll 1
    for (int c = 0; c < NCH; ++c) {
        const int s = c & 1;
        asm volatile("cp.async.wait_group 0;" ::: "memory");
        __syncthreads();
        if (c + 1 < NCH) load2(smbase, 1 - s, aP, as, bP, bs, k0 + (c + 1) * 32, tid);
        gemm_tf32(smbase + s * STAGE_B, smbase + s * STAGE_B + MATB, wm, wn, lane, acc);
    }
}

// ---------------- K/V projection: grid (4, 256, 2) ----------------
// out eKT[d,n] (mz==1, +row sums) or VT[e,n] (mz==2).
__global__ __launch_bounds__(256, 2)
void projkv_kernel(const float* __restrict__ xk, const float* __restrict__ xv,
                   const float* __restrict__ bk, const float* __restrict__ bvv) {
    extern __shared__ char smx[];
    const uint32_t smbase = smem_u32(smx);
    const int tid = threadIdx.x, wid = tid >> 5, lane = tid & 31;
    const int wm = wid & 1, wn = wid >> 1;
    const int mz = blockIdx.z + 1;
    const int byr = blockIdx.y, dtile = blockIdx.x;
    const int b = byr >> 5, ntile = byr & 31;

    const float* X = (mz == 1) ? xk : xv;
    const float* bias = (mz == 1) ? bk : bvv;
    const float* Wp = g_Wt + (size_t)mz * DM * DM;
    const float* xP = X + ((size_t)b * 4096 + (size_t)ntile * 128) * 512;
    const float* wP = Wp + (size_t)dtile * 128 * 512;

    float acc[4][4][4];
#pragma unroll
    for (int a = 0; a < 4; ++a)
#pragma unroll
        for (int b2 = 0; b2 < 4; ++b2)
#pragma unroll
            for (int c = 0; c < 4; ++c) acc[a][b2][c] = 0.f;

    mainloop2<16>(smbase, wP, 512, xP, 512, 0, tid, wm, wn, lane, acc);
    __syncthreads();

    const int r0 = wm * 64 + (lane >> 2);
    const int c0 = wn * 32 + (lane & 3) * 2;

    float brow[4][2];
#pragma unroll
    for (int mt = 0; mt < 4; ++mt)
#pragma unroll
        for (int p = 0; p < 2; ++p)
            brow[mt][p] = bias[dtile * 128 + r0 + mt * 16 + p * 8];

    float ps[4][2];
#pragma unroll
    for (int a = 0; a < 4; ++a) { ps[a][0] = 0.f; ps[a][1] = 0.f; }

    char* st = smx;
#pragma unroll
    for (int mt = 0; mt < 4; ++mt)
#pragma unroll
        for (int nt = 0; nt < 4; ++nt)
#pragma unroll
            for (int p = 0; p < 2; ++p) {
                float v0 = acc[mt][nt][p * 2] + brow[mt][p];
                float v1 = acc[mt][nt][p * 2 + 1] + brow[mt][p];
                if (mz == 1) {
                    v0 = __expf(v0 * kINVS);
                    v1 = __expf(v1 * kINVS);
                }
                v0 = rtf(v0); v1 = rtf(v1);
                if (mz == 1) ps[mt][p] += v0 + v1;
                const int row = r0 + mt * 16 + p * 8;
                const int col = c0 + nt * 8;
                float2 o; o.x = v0; o.y = v1;
                *reinterpret_cast<float2*>(st + row * SPB2 + col * 4) = o;
            }

    float* sW = reinterpret_cast<float*>(smx + SW_OFF);
    if (mz == 1) {
#pragma unroll
        for (int mt = 0; mt < 4; ++mt)
#pragma unroll
            for (int p = 0; p < 2; ++p) {
                ps[mt][p] += __shfl_xor_sync(0xffffffffu, ps[mt][p], 1);
                ps[mt][p] += __shfl_xor_sync(0xffffffffu, ps[mt][p], 2);
            }
        if ((lane & 3) == 0) {
#pragma unroll
            for (int mt = 0; mt < 4; ++mt)
#pragma unroll
                for (int p = 0; p < 2; ++p)
                    sW[wn * 128 + wm * 64 + mt * 16 + p * 8 + (lane >> 2)] = ps[mt][p];
        }
    }
    __syncthreads();

    float* outP = (mz == 1) ? g_eKT : g_VT;
    const size_t base = ((size_t)b * 512 + dtile * 128) * 4096 + (size_t)ntile * 128;
#pragma unroll
    for (int it = 0; it < 16; ++it) {
        const int idx = tid + it * 256, row = idx >> 5, seg = idx & 31;
        const float4 v = *reinterpret_cast<const float4*>(st + row * SPB2 + seg * 16);
        *reinterpret_cast<float4*>(outP + base + (size_t)row * 4096 + seg * 4) = v;
    }
    if (mz == 1 && tid < 128)
        g_pk[((size_t)b * 32 + ntile) * 512 + dtile * 128 + tid] =
            sW[tid] + sW[128 + tid] + sW[256 + tid] + sW[384 + tid];
}

// ---------------- merged projQ + bm_split: grid 1536 ----------------
// CTAs [0,1024): eQ[n,d] = exp((xq@Wq+b)*s) (+col sums)
// CTAs [1024,1536): bm partials (split-K x4) — needs only eKT / VT.
__global__ __launch_bounds__(256, 2)
void projq_bm_kernel(const float* __restrict__ xq, const float* __restrict__ bq) {
    extern __shared__ char smx[];
    const uint32_t smbase = smem_u32(smx);
    const int tid = threadIdx.x, wid = tid >> 5, lane = tid & 31;
    const int wm = wid & 1, wn = wid >> 1;
    const int t = blockIdx.x;

    float acc[4][4][4];
#pragma unroll
    for (int a = 0; a < 4; ++a)
#pragma unroll
        for (int b2 = 0; b2 < 4; ++b2)
#pragma unroll
            for (int c = 0; c < 4; ++c) acc[a][b2][c] = 0.f;

    const int r0 = wm * 64 + (lane >> 2);
    const int c0 = wn * 32 + (lane & 3) * 2;

    if (t < 1024) {
        // ---- projQ ----
        const int bx = t & 3, byr = t >> 2;
        const float* xP = xq + (size_t)byr * 128 * 512;
        const float* wP = g_Wt + (size_t)bx * 128 * 512;
        mainloop2<16>(smbase, xP, 512, wP, 512, 0, tid, wm, wn, lane, acc);
        __syncthreads();

        float bcol[4][2];
#pragma unroll
        for (int nt = 0; nt < 4; ++nt) {
            const int cc = bx * 128 + c0 + nt * 8;
            bcol[nt][0] = bq[cc]; bcol[nt][1] = bq[cc + 1];
        }
        float ps[4][2];
#pragma unroll
        for (int a = 0; a < 4; ++a) { ps[a][0] = 0.f; ps[a][1] = 0.f; }

        char* st = smx;
#pragma unroll
        for (int mt = 0; mt < 4; ++mt)
#pragma unroll
            for (int nt = 0; nt < 4; ++nt)
#pragma unroll
                for (int p = 0; p < 2; ++p) {
                    float v0 = __expf((acc[mt][nt][p * 2]     + bcol[nt][0]) * kINVS);
                    float v1 = __expf((acc[mt][nt][p * 2 + 1] + bcol[nt][1]) * kINVS);
                    v0 = rtf(v0); v1 = rtf(v1);
                    ps[nt][0] += v0; ps[nt][1] += v1;
                    const int row = r0 + mt * 16 + p * 8;
                    const int col = c0 + nt * 8;
                    float2 o; o.x = v0; o.y = v1;
                    *reinterpret_cast<float2*>(st + row * SPB2 + col * 4) = o;
                }

        float* sW = reinterpret_cast<float*>(smx + SW_OFF);
#pragma unroll
        for (int nt = 0; nt < 4; ++nt)
#pragma unroll
            for (int j = 0; j < 2; ++j) {
                ps[nt][j] += __shfl_xor_sync(0xffffffffu, ps[nt][j], 4);
                ps[nt][j] += __shfl_xor_sync(0xffffffffu, ps[nt][j], 8);
                ps[nt][j] += __shfl_xor_sync(0xffffffffu, ps[nt][j], 16);
            }
        if ((lane >> 2) == 0) {
#pragma unroll
            for (int nt = 0; nt < 4; ++nt)
#pragma unroll
                for (int j = 0; j < 2; ++j)
                    sW[wm * 128 + wn * 32 + nt * 8 + (lane & 3) * 2 + j] = ps[nt][j];
        }
        __syncthreads();

        const size_t base = (size_t)byr * 128 * 512 + bx * 128;
#pragma unroll
        for (int it = 0; it < 16; ++it) {
            const int idx = tid + it * 256, row = idx >> 5, seg = idx & 31;
            const float4 v = *reinterpret_cast<const float4*>(st + row * SPB2 + seg * 16);
            *reinterpret_cast<float4*>(g_eQ + base + (size_t)row * 512 + seg * 4) = v;
        }
        if (tid < 128)
            g_pq[(size_t)byr * 512 + bx * 128 + tid] = sW[tid] + sW[128 + tid];
    } else {
        // ---- bm split-K x4 ----
        const int u = t - 1024;
        const int bx = u & 3, y = (u >> 2) & 15, bz = u >> 6;
        const int split = y >> 2, ey = y & 3;
        const int k0 = split * 1024;

        const float* aP = g_VT + ((size_t)bz * 512 + ey * 128) * 4096;
        const float* bP = g_eKT + ((size_t)bz * 512 + bx * 128) * 4096;

        mainloop2<32>(smbase, aP, 4096, bP, 4096, k0, tid, wm, wn, lane, acc);

        float* outP = g_BmP + ((size_t)split * 8 + bz) * DM * DM;
#pragma unroll
        for (int mt = 0; mt < 4; ++mt)
#pragma unroll
            for (int nt = 0; nt < 4; ++nt)
#pragma unroll
                for (int p = 0; p < 2; ++p) {
                    const int e = ey * 128 + r0 + mt * 16 + p * 8;
                    const int d = bx * 128 + c0 + nt * 8;
                    float2 o;
                    o.x = acc[mt][nt][p * 2];
                    o.y = acc[mt][nt][p * 2 + 1];
                    *reinterpret_cast<float2*>(outP + (size_t)e * DM + d) = o;
                }
    }
}

// ---------------- combine sums ----------------
__global__ __launch_bounds__(512)
void combine_sums_kernel() {
    const int i = blockIdx.x * 512 + threadIdx.x;
    const int b = i >> 9, d = i & 511;
    float q = 0.f, k = 0.f;
#pragma unroll
    for (int j = 0; j < 32; ++j) {
        q += g_pq[(b * 32 + j) * 512 + d];
        k += g_pk[(b * 32 + j) * 512 + d];
    }
    g_sum[i] = q;
    g_sum[4096 + i] = k;
}

// ---------------- Bm combine: sum, scale, round ----------------
__global__ __launch_bounds__(256)
void bm_combine_kernel() {
    const size_t idx = (size_t)blockIdx.x * 256 + threadIdx.x;
    const size_t e4 = idx * 4;
    const int bz = (int)(e4 >> 18);
    const int d0 = (int)(e4 & 511);
    float4 s = reinterpret_cast<const float4*>(g_BmP)[idx];
#pragma unroll
    for (int sp = 1; sp < 4; ++sp) {
        const float4 t = reinterpret_cast<const float4*>(g_BmP + (size_t)sp * 8 * DM * DM)[idx];
        s.x += t.x; s.y += t.y; s.z += t.z; s.w += t.w;
    }
    const float* sq = g_sum + bz * 512 + d0;
    const float* sk = g_sum + 4096 + bz * 512 + d0;
    s.x = rtf(s.x / (sk[0] * sq[0]));
    s.y = rtf(s.y / (sk[1] * sq[1]));
    s.z = rtf(s.z / (sk[2] * sq[2]));
    s.w = rtf(s.w / (sk[3] * sq[3]));
    reinterpret_cast<float4*>(g_BmT)[idx] = s;
}

// ---------------- Z GEMM: grid (4, 32, 8) ----------------
__global__ __launch_bounds__(256, 2)
void z_gemm_kernel(float* __restrict__ Z) {
    extern __shared__ char smx[];
    const uint32_t smbase = smem_u32(smx);
    const int tid = threadIdx.x, wid = tid >> 5, lane = tid & 31;
    const int wm = wid & 1, wn = wid >> 1;
    const int bx = blockIdx.x, by = blockIdx.y, bz = blockIdx.z;

    const float* aP = g_eQ + ((size_t)bz * 4096 + by * 128) * 512;
    const float* bP = g_BmT + ((size_t)bz * 512 + bx * 128) * 512;

    float acc[4][4][4];
#pragma unroll
    for (int a = 0; a < 4; ++a)
#pragma unroll
        for (int b2 = 0; b2 < 4; ++b2)
#pragma unroll
            for (int c = 0; c < 4; ++c) acc[a][b2][c] = 0.f;

    mainloop2<16>(smbase, aP, 512, bP, 512, 0, tid, wm, wn, lane, acc);

    const int r0 = wm * 64 + (lane >> 2);
    const int c0 = wn * 32 + (lane & 3) * 2;
#pragma unroll
    for (int mt = 0; mt < 4; ++mt)
#pragma unroll
        for (int nt = 0; nt < 4; ++nt)
#pragma unroll
            for (int p = 0; p < 2; ++p) {
                const int cc = bx * 128 + c0 + nt * 8;
                const size_t row = (size_t)bz * 4096 + by * 128 + r0 + mt * 16 + p * 8;
                float2 o;
                o.x = acc[mt][nt][p * 2];
                o.y = acc[mt][nt][p * 2 + 1];
                *reinterpret_cast<float2*>(Z + row * 512 + cc) = o;
            }
}

// ---------------- weight transpose + tf32 round ----------------
__global__ __launch_bounds__(256)
void wt_round_kernel(const float* __restrict__ w0, const float* __restrict__ w1,
                     const float* __restrict__ w2) {
    __shared__ float t[32][33];
    const int mz = blockIdx.z;
    const float* src = (mz == 0) ? w0 : (mz == 1) ? w1 : w2;
    float* dst = g_Wt + (size_t)mz * DM * DM;
    const int c0 = blockIdx.x * 32, r0 = blockIdx.y * 32;
#pragma unroll
    for (int i = 0; i < 4; ++i) {
        const int r = r0 + threadIdx.y + i * 8;
        t[threadIdx.y + i * 8][threadIdx.x] = src[(size_t)r * DM + c0 + threadIdx.x];
    }
    __syncthreads();
#pragma unroll
    for (int i = 0; i < 4; ++i) {
        const int c = c0 + threadIdx.y + i * 8;
        const int r = r0 + threadIdx.x;
        dst[(size_t)c * DM + r] = rtf(t[threadIdx.x][threadIdx.y + i * 8]);
    }
}

// ---------------- launch ----------------
extern "C" void kernel_launch(void* const* d_in, const int* in_sizes, int n_in,
                              void* d_out, int out_size) {
    const float* x_q = (const float*)d_in[0];
    const float* x_k = (const float*)d_in[1];
    const float* x_v = (const float*)d_in[2];
    const float* W_q = (const float*)d_in[3];
    const float* b_q = (const float*)d_in[4];
    const float* W_k = (const float*)d_in[5];
    const float* b_k = (const float*)d_in[6];
    const float* W_v = (const float*)d_in[7];
    const float* b_v = (const float*)d_in[8];
    float* Z = (float*)d_out;

    cudaFuncSetAttribute(projkv_kernel, cudaFuncAttributeMaxDynamicSharedMemorySize, SMEM_BYTES);
    cudaFuncSetAttribute(projq_bm_kernel, cudaFuncAttributeMaxDynamicSharedMemorySize, SMEM_BYTES);
    cudaFuncSetAttribute(z_gemm_kernel, cudaFuncAttributeMaxDynamicSharedMemorySize, SMEM_BYTES);

    wt_round_kernel<<<dim3(16, 16, 3), dim3(32, 8)>>>(W_q, W_k, W_v);

    projkv_kernel<<<dim3(4, 256, 2), 256, SMEM_BYTES>>>(x_k, x_v, b_k, b_v);

    projq_bm_kernel<<<1536, 256, SMEM_BYTES>>>(x_q, b_q);

    combine_sums_kernel<<<8, 512>>>();
    bm_combine_kernel<<<2048, 256>>>();

    z_gemm_kernel<<<dim3(4, 32, 8), 256, SMEM_BYTES>>>(Z);
}

// round 11
// speedup vs baseline: 1.0079x; 1.0079x over previous
#include <cuda_runtime.h>
#include <cuda_bf16.h>
#include <stdint.h>

// ============================================================================
// LightAttention via mma.sync m16n8k8 TF32. CTA = 128 threads (4 warps, 2x2),
// tile 128(M)x64(N), 4 CTAs/SM (4 independent barrier domains per SM).
//   projq : eQ[n,d]=exp((xq@Wq+b)*s) (+col-sum partials)
//   projkv: eKT[d,n]=exp((xk@Wk+b)^T*s) (+row sums); VT[e,n]=(xv@Wv+b)^T
//   combine_sums; bm_split (split-K x2, one wave); bm_combine; z_gemm.
// W/intermediates RNE-rounded to tf32; x raw fp32 (truncation unbiased vs W).
// Softmax max dropped (exp args in [-0.75,0.75]; cancels algebraically).
// ============================================================================

#define B_SZ   8
#define N_SEQ  4096
#define DM     512
#define M_ALL  (B_SZ * N_SEQ)
#define ELTS   ((size_t)M_ALL * DM)

static __device__ __constant__ float kINVS = 0.21022410381342863f; // 512^-0.25

// ---------------- scratch ----------------
__device__ __align__(16) float g_Wt[3 * DM * DM];
__device__ __align__(16) float g_eQ[ELTS];
__device__ __align__(16) float g_eKT[ELTS];
__device__ __align__(16) float g_VT[ELTS];
__device__ __align__(16) float g_BmT[B_SZ * DM * DM];
__device__ __align__(16) float g_BmP[2 * B_SZ * DM * DM];
__device__ float g_pq[256 * DM];
__device__ float g_pk[8 * 64 * DM];
__device__ float g_sum[2 * B_SZ * DM];

// ---------------- helpers ----------------
__device__ __forceinline__ uint32_t smem_u32(const void* p) {
    uint32_t r;
    asm("{ .reg .u64 t; cvta.to.shared.u64 t, %1; cvt.u32.u64 %0, t; }" : "=r"(r) : "l"(p));
    return r;
}
// RNE round fp32 -> tf32
__device__ __forceinline__ float rtf(float x) {
    uint32_t u = __float_as_uint(x);
    u = (u + 0x00000FFFu + ((u >> 13) & 1u)) & 0xFFFFE000u;
    return __uint_as_float(u);
}
__device__ __forceinline__ void ldmx4(uint32_t r[4], uint32_t addr) {
    asm volatile("ldmatrix.sync.aligned.m8n8.x4.shared.b16 {%0,%1,%2,%3}, [%4];"
                 : "=r"(r[0]), "=r"(r[1]), "=r"(r[2]), "=r"(r[3]) : "r"(addr));
}
__device__ __forceinline__ void mmatf32(float c[4], const uint32_t a[4],
                                        uint32_t b0, uint32_t b1) {
    asm volatile("mma.sync.aligned.m16n8k8.row.col.f32.tf32.tf32.f32 "
                 "{%0,%1,%2,%3}, {%4,%5,%6,%7}, {%8,%9}, {%0,%1,%2,%3};"
                 : "+f"(c[0]), "+f"(c[1]), "+f"(c[2]), "+f"(c[3])
                 : "r"(a[0]), "r"(a[1]), "r"(a[2]), "r"(a[3]), "r"(b0), "r"(b1));
}

#define PITCH    144            // 32 fp32 (128B) + 16B pad
#define A_MATB   18432          // 128 * 144
#define B_MATB   9216           // 64 * 144
#define STAGE_B  27648
#define SMEM_BYTES 55296        // 2 stages
#define SPB2     272            // staging pitch: 64 fp32 + 16B pad
#define SW_OFF   34816

// k32 chunk: A[128,32] @ B[64,32]^T, warps 2(M)x2(N), warp tile 64x32.
__device__ __forceinline__ void gemm_tf32(uint32_t aBase, uint32_t bBase,
                                          int wm, int wn, int lane, float acc[4][4][4]) {
    const int arow = wm * 64 + (lane & 15);
    const int brow = wn * 32 + (lane & 15);
    const uint32_t lhi = (uint32_t)((lane >> 4) * 16);
#pragma unroll
    for (int s8 = 0; s8 < 4; ++s8) {
        const uint32_t kb = (uint32_t)(s8 * 32) + lhi;
        uint32_t a[4][4], b[2][4];
#pragma unroll
        for (int mt = 0; mt < 4; ++mt)
            ldmx4(a[mt], aBase + (uint32_t)(arow + mt * 16) * PITCH + kb);
#pragma unroll
        for (int ng = 0; ng < 2; ++ng)
            ldmx4(b[ng], bBase + (uint32_t)(brow + ng * 16) * PITCH + kb);
#pragma unroll
        for (int mt = 0; mt < 4; ++mt)
#pragma unroll
            for (int nt = 0; nt < 4; ++nt)
                mmatf32(acc[mt][nt], a[mt], b[nt >> 1][nt & 1], b[nt >> 1][(nt & 1) + 2]);
    }
}

// ---------------- async stage loader: A 128 rows + B 64 rows ----------------
__device__ __forceinline__ void load2(uint32_t smbase, int s,
                                      const float* aP, int as,
                                      const float* bP, int bs, int kc, int tid) {
    const uint32_t base = smbase + s * STAGE_B;
#pragma unroll
    for (int i = 0; i < 8; ++i) {
        const int idx = tid + i * 128, row = idx >> 3, c16 = idx & 7;
        const uint32_t d = base + row * PITCH + c16 * 16;
        const float* g = aP + (size_t)row * as + kc + c16 * 4;
        asm volatile("cp.async.cg.shared.global [%0], [%1], 16;" :: "r"(d), "l"(g));
    }
#pragma unroll
    for (int i = 0; i < 4; ++i) {
        const int idx = tid + i * 128, row = idx >> 3, c16 = idx & 7;
        const uint32_t d = base + A_MATB + row * PITCH + c16 * 16;
        const float* g = bP + (size_t)row * bs + kc + c16 * 4;
        asm volatile("cp.async.cg.shared.global [%0], [%1], 16;" :: "r"(d), "l"(g));
    }
    asm volatile("cp.async.commit_group;");
}

// 2-stage mainloop over NCH chunks of K=32 starting at k0.
template<int NCH>
__device__ __forceinline__ void mainloop2(uint32_t smbase,
                                          const float* aP, int as,
                                          const float* bP, int bs, int k0,
                                          int tid, int wm, int wn, int lane,
                                          float acc[4][4][4]) {
    load2(smbase, 0, aP, as, bP, bs, k0, tid);
#pragma unroll 1
    for (int c = 0; c < NCH; ++c) {
        const int s = c & 1;
        asm volatile("cp.async.wait_group 0;" ::: "memory");
        __syncthreads();
        if (c + 1 < NCH) load2(smbase, 1 - s, aP, as, bP, bs, k0 + (c + 1) * 32, tid);
        gemm_tf32(smbase + s * STAGE_B, smbase + s * STAGE_B + A_MATB, wm, wn, lane, acc);
    }
}

// ---------------- Q projection: grid (8, 256) ----------------
// A = xq rows [byr*128,+128), B = Wq rows [bx*64,+64); out eQ[n,d] + col sums.
__global__ __launch_bounds__(128, 4)
void projq_kernel(const float* __restrict__ xq, const float* __restrict__ bq) {
    extern __shared__ char smx[];
    const uint32_t smbase = smem_u32(smx);
    const int tid = threadIdx.x, wid = tid >> 5, lane = tid & 31;
    const int wm = wid & 1, wn = wid >> 1;
    const int bx = blockIdx.x, byr = blockIdx.y;

    const float* xP = xq + (size_t)byr * 128 * 512;
    const float* wP = g_Wt + (size_t)bx * 64 * 512;

    float acc[4][4][4];
#pragma unroll
    for (int a = 0; a < 4; ++a)
#pragma unroll
        for (int b2 = 0; b2 < 4; ++b2)
#pragma unroll
            for (int c = 0; c < 4; ++c) acc[a][b2][c] = 0.f;

    mainloop2<16>(smbase, xP, 512, wP, 512, 0, tid, wm, wn, lane, acc);
    __syncthreads();

    const int r0 = wm * 64 + (lane >> 2);
    const int c0 = wn * 32 + (lane & 3) * 2;

    float bcol[4][2];
#pragma unroll
    for (int nt = 0; nt < 4; ++nt) {
        const int cc = bx * 64 + c0 + nt * 8;
        bcol[nt][0] = bq[cc]; bcol[nt][1] = bq[cc + 1];
    }
    float ps[4][2];
#pragma unroll
    for (int a = 0; a < 4; ++a) { ps[a][0] = 0.f; ps[a][1] = 0.f; }

    char* st = smx;
#pragma unroll
    for (int mt = 0; mt < 4; ++mt)
#pragma unroll
        for (int nt = 0; nt < 4; ++nt)
#pragma unroll
            for (int p = 0; p < 2; ++p) {
                float v0 = rtf(__expf((acc[mt][nt][p * 2]     + bcol[nt][0]) * kINVS));
                float v1 = rtf(__expf((acc[mt][nt][p * 2 + 1] + bcol[nt][1]) * kINVS));
                ps[nt][0] += v0; ps[nt][1] += v1;
                const int row = r0 + mt * 16 + p * 8;
                const int col = c0 + nt * 8;
                float2 o; o.x = v0; o.y = v1;
                *reinterpret_cast<float2*>(st + row * SPB2 + col * 4) = o;
            }

    float* sW = reinterpret_cast<float*>(smx + SW_OFF);
#pragma unroll
    for (int nt = 0; nt < 4; ++nt)
#pragma unroll
        for (int j = 0; j < 2; ++j) {
            ps[nt][j] += __shfl_xor_sync(0xffffffffu, ps[nt][j], 4);
            ps[nt][j] += __shfl_xor_sync(0xffffffffu, ps[nt][j], 8);
            ps[nt][j] += __shfl_xor_sync(0xffffffffu, ps[nt][j], 16);
        }
    if ((lane >> 2) == 0) {
#pragma unroll
        for (int nt = 0; nt < 4; ++nt)
#pragma unroll
            for (int j = 0; j < 2; ++j)
                sW[wm * 64 + wn * 32 + nt * 8 + (lane & 3) * 2 + j] = ps[nt][j];
    }
    __syncthreads();

    const size_t base = (size_t)byr * 128 * 512 + bx * 64;
#pragma unroll
    for (int it = 0; it < 16; ++it) {
        const int idx = tid + it * 128, row = idx >> 4, seg = idx & 15;
        const float4 v = *reinterpret_cast<const float4*>(st + row * SPB2 + seg * 16);
        *reinterpret_cast<float4*>(g_eQ + base + (size_t)row * 512 + seg * 4) = v;
    }
    if (tid < 64)
        g_pq[(size_t)byr * 512 + bx * 64 + tid] = sW[tid] + sW[64 + tid];
}

// ---------------- K/V projection: grid (4, 512, 2) ----------------
// A = W rows [bx*128,+128), B = x rows 64; out [d,n] / [e,n] (+K row sums).
__global__ __launch_bounds__(128, 4)
void projkv_kernel(const float* __restrict__ xk, const float* __restrict__ xv,
                   const float* __restrict__ bk, const float* __restrict__ bvv) {
    extern __shared__ char smx[];
    const uint32_t smbase = smem_u32(smx);
    const int tid = threadIdx.x, wid = tid >> 5, lane = tid & 31;
    const int wm = wid & 1, wn = wid >> 1;
    const int isK = (blockIdx.z == 0);
    const int bx = blockIdx.x;                 // d-tile (128)
    const int b = blockIdx.y >> 6, ntile = blockIdx.y & 63;

    const float* X = isK ? xk : xv;
    const float* bias = isK ? bk : bvv;
    const float* wP = g_Wt + (size_t)(isK ? 1 : 2) * DM * DM + (size_t)bx * 128 * 512;
    const float* xP = X + ((size_t)b * 4096 + (size_t)ntile * 64) * 512;

    float acc[4][4][4];
#pragma unroll
    for (int a = 0; a < 4; ++a)
#pragma unroll
        for (int b2 = 0; b2 < 4; ++b2)
#pragma unroll
            for (int c = 0; c < 4; ++c) acc[a][b2][c] = 0.f;

    mainloop2<16>(smbase, wP, 512, xP, 512, 0, tid, wm, wn, lane, acc);
    __syncthreads();

    const int r0 = wm * 64 + (lane >> 2);
    const int c0 = wn * 32 + (lane & 3) * 2;

    float brow[4][2];
#pragma unroll
    for (int mt = 0; mt < 4; ++mt)
#pragma unroll
        for (int p = 0; p < 2; ++p)
            brow[mt][p] = bias[bx * 128 + r0 + mt * 16 + p * 8];

    float ps[4][2];
#pragma unroll
    for (int a = 0; a < 4; ++a) { ps[a][0] = 0.f; ps[a][1] = 0.f; }

    char* st = smx;
#pragma unroll
    for (int mt = 0; mt < 4; ++mt)
#pragma unroll
        for (int nt = 0; nt < 4; ++nt)
#pragma unroll
            for (int p = 0; p < 2; ++p) {
                float v0 = acc[mt][nt][p * 2] + brow[mt][p];
                float v1 = acc[mt][nt][p * 2 + 1] + brow[mt][p];
                if (isK) {
                    v0 = __expf(v0 * kINVS);
                    v1 = __expf(v1 * kINVS);
                }
                v0 = rtf(v0); v1 = rtf(v1);
                if (isK) ps[mt][p] += v0 + v1;
                const int row = r0 + mt * 16 + p * 8;
                const int col = c0 + nt * 8;
                float2 o; o.x = v0; o.y = v1;
                *reinterpret_cast<float2*>(st + row * SPB2 + col * 4) = o;
            }

    float* sW = reinterpret_cast<float*>(smx + SW_OFF);
    if (isK) {
#pragma unroll
        for (int mt = 0; mt < 4; ++mt)
#pragma unroll
            for (int p = 0; p < 2; ++p) {
                ps[mt][p] += __shfl_xor_sync(0xffffffffu, ps[mt][p], 1);
                ps[mt][p] += __shfl_xor_sync(0xffffffffu, ps[mt][p], 2);
            }
        if ((lane & 3) == 0) {
#pragma unroll
            for (int mt = 0; mt < 4; ++mt)
#pragma unroll
                for (int p = 0; p < 2; ++p)
                    sW[wn * 128 + wm * 64 + mt * 16 + p * 8 + (lane >> 2)] = ps[mt][p];
        }
    }
    __syncthreads();

    float* outP = isK ? g_eKT : g_VT;
    const size_t base = ((size_t)b * 512 + bx * 128) * 4096 + (size_t)ntile * 64;
#pragma unroll
    for (int it = 0; it < 16; ++it) {
        const int idx = tid + it * 128, row = idx >> 4, seg = idx & 15;
        const float4 v = *reinterpret_cast<const float4*>(st + row * SPB2 + seg * 16);
        *reinterpret_cast<float4*>(outP + base + (size_t)row * 4096 + seg * 4) = v;
    }
    if (isK && tid < 128)
        g_pk[((size_t)b * 64 + ntile) * 512 + bx * 128 + tid] = sW[tid] + sW[128 + tid];
}

// ---------------- combine sums ----------------
__global__ __launch_bounds__(512)
void combine_sums_kernel() {
    const int i = blockIdx.x * 512 + threadIdx.x;
    const int b = i >> 9, d = i & 511;
    float q = 0.f, k = 0.f;
#pragma unroll
    for (int j = 0; j < 32; ++j) q += g_pq[(b * 32 + j) * 512 + d];
#pragma unroll
    for (int j = 0; j < 64; ++j) k += g_pk[(b * 64 + j) * 512 + d];
    g_sum[i] = q;
    g_sum[4096 + i] = k;
}

// ---------------- Bm split-K x2: grid (8, 4, 16) = 512 CTAs (one wave) ------
__global__ __launch_bounds__(128, 4)
void bm_split_kernel() {
    extern __shared__ char smx[];
    const uint32_t smbase = smem_u32(smx);
    const int tid = threadIdx.x, wid = tid >> 5, lane = tid & 31;
    const int wm = wid & 1, wn = wid >> 1;
    const int bx = blockIdx.x, ey = blockIdx.y;
    const int b = blockIdx.z >> 1, split = blockIdx.z & 1;
    const int k0 = split * 2048;

    const float* aP = g_VT + ((size_t)b * 512 + ey * 128) * 4096;
    const float* bP = g_eKT + ((size_t)b * 512 + bx * 64) * 4096;

    float acc[4][4][4];
#pragma unroll
    for (int a = 0; a < 4; ++a)
#pragma unroll
        for (int b2 = 0; b2 < 4; ++b2)
#pragma unroll
            for (int c = 0; c < 4; ++c) acc[a][b2][c] = 0.f;

    mainloop2<64>(smbase, aP, 4096, bP, 4096, k0, tid, wm, wn, lane, acc);

    const int r0 = wm * 64 + (lane >> 2);
    const int c0 = wn * 32 + (lane & 3) * 2;
    float* outP = g_BmP + ((size_t)split * 8 + b) * DM * DM;
#pragma unroll
    for (int mt = 0; mt < 4; ++mt)
#pragma unroll
        for (int nt = 0; nt < 4; ++nt)
#pragma unroll
            for (int p = 0; p < 2; ++p) {
                const int e = ey * 128 + r0 + mt * 16 + p * 8;
                const int d = bx * 64 + c0 + nt * 8;
                float2 o;
                o.x = acc[mt][nt][p * 2];
                o.y = acc[mt][nt][p * 2 + 1];
                *reinterpret_cast<float2*>(outP + (size_t)e * DM + d) = o;
            }
}

// ---------------- Bm combine: sum 2 partials, scale, round ----------------
__global__ __launch_bounds__(256)
void bm_combine_kernel() {
    const size_t idx = (size_t)blockIdx.x * 256 + threadIdx.x;
    const size_t e4 = idx * 4;
    const int bz = (int)(e4 >> 18);
    const int d0 = (int)(e4 & 511);
    float4 s = reinterpret_cast<const float4*>(g_BmP)[idx];
    const float4 t = reinterpret_cast<const float4*>(g_BmP + (size_t)8 * DM * DM)[idx];
    s.x += t.x; s.y += t.y; s.z += t.z; s.w += t.w;
    const float* sq = g_sum + bz * 512 + d0;
    const float* sk = g_sum + 4096 + bz * 512 + d0;
    s.x = rtf(s.x / (sk[0] * sq[0]));
    s.y = rtf(s.y / (sk[1] * sq[1]));
    s.z = rtf(s.z / (sk[2] * sq[2]));
    s.w = rtf(s.w / (sk[3] * sq[3]));
    reinterpret_cast<float4*>(g_BmT)[idx] = s;
}

// ---------------- Z GEMM: grid (8, 32, 8) ----------------
__global__ __launch_bounds__(128, 4)
void z_gemm_kernel(float* __restrict__ Z) {
    extern __shared__ char smx[];
    const uint32_t smbase = smem_u32(smx);
    const int tid = threadIdx.x, wid = tid >> 5, lane = tid & 31;
    const int wm = wid & 1, wn = wid >> 1;
    const int bx = blockIdx.x, by = blockIdx.y, bz = blockIdx.z;

    const float* aP = g_eQ + ((size_t)bz * 4096 + by * 128) * 512;
    const float* bP = g_BmT + ((size_t)bz * 512 + bx * 64) * 512;

    float acc[4][4][4];
#pragma unroll
    for (int a = 0; a < 4; ++a)
#pragma unroll
        for (int b2 = 0; b2 < 4; ++b2)
#pragma unroll
            for (int c = 0; c < 4; ++c) acc[a][b2][c] = 0.f;

    mainloop2<16>(smbase, aP, 512, bP, 512, 0, tid, wm, wn, lane, acc);

    const int r0 = wm * 64 + (lane >> 2);
    const int c0 = wn * 32 + (lane & 3) * 2;
#pragma unroll
    for (int mt = 0; mt < 4; ++mt)
#pragma unroll
        for (int nt = 0; nt < 4; ++nt)
#pragma unroll
            for (int p = 0; p < 2; ++p) {
                const int cc = bx * 64 + c0 + nt * 8;
                const size_t row = (size_t)bz * 4096 + by * 128 + r0 + mt * 16 + p * 8;
                float2 o;
                o.x = acc[mt][nt][p * 2];
                o.y = acc[mt][nt][p * 2 + 1];
                *reinterpret_cast<float2*>(Z + row * 512 + cc) = o;
            }
}

// ---------------- weight transpose + tf32 round ----------------
__global__ __launch_bounds__(256)
void wt_round_kernel(const float* __restrict__ w0, const float* __restrict__ w1,
                     const float* __restrict__ w2) {
    __shared__ float t[32][33];
    const int mz = blockIdx.z;
    const float* src = (mz == 0) ? w0 : (mz == 1) ? w1 : w2;
    float* dst = g_Wt + (size_t)mz * DM * DM;
    const int c0 = blockIdx.x * 32, r0 = blockIdx.y * 32;
#pragma unroll
    for (int i = 0; i < 4; ++i) {
        const int r = r0 + threadIdx.y + i * 8;
        t[threadIdx.y + i * 8][threadIdx.x] = src[(size_t)r * DM + c0 + threadIdx.x];
    }
    __syncthreads();
#pragma unroll
    for (int i = 0; i < 4; ++i) {
        const int c = c0 + threadIdx.y + i * 8;
        const int r = r0 + threadIdx.x;
        dst[(size_t)c * DM + r] = rtf(t[threadIdx.x][threadIdx.y + i * 8]);
    }
}

// ---------------- launch ----------------
extern "C" void kernel_launch(void* const* d_in, const int* in_sizes, int n_in,
                              void* d_out, int out_size) {
    const float* x_q = (const float*)d_in[0];
    const float* x_k = (const float*)d_in[1];
    const float* x_v = (const float*)d_in[2];
    const float* W_q = (const float*)d_in[3];
    const float* b_q = (const float*)d_in[4];
    const float* W_k = (const float*)d_in[5];
    const float* b_k = (const float*)d_in[6];
    const float* W_v = (const float*)d_in[7];
    const float* b_v = (const float*)d_in[8];
    float* Z = (float*)d_out;

    cudaFuncSetAttribute(projq_kernel, cudaFuncAttributeMaxDynamicSharedMemorySize, SMEM_BYTES);
    cudaFuncSetAttribute(projkv_kernel, cudaFuncAttributeMaxDynamicSharedMemorySize, SMEM_BYTES);
    cudaFuncSetAttribute(bm_split_kernel, cudaFuncAttributeMaxDynamicSharedMemorySize, SMEM_BYTES);
    cudaFuncSetAttribute(z_gemm_kernel, cudaFuncAttributeMaxDynamicSharedMemorySize, SMEM_BYTES);

    wt_round_kernel<<<dim3(16, 16, 3), dim3(32, 8)>>>(W_q, W_k, W_v);

    projkv_kernel<<<dim3(4, 512, 2), 128, SMEM_BYTES>>>(x_k, x_v, b_k, b_v);
    projq_kernel<<<dim3(8, 256), 128, SMEM_BYTES>>>(x_q, b_q);

    combine_sums_kernel<<<8, 512>>>();

    bm_split_kernel<<<dim3(8, 4, 16), 128, SMEM_BYTES>>>();
    bm_combine_kernel<<<2048, 256>>>();

    z_gemm_kernel<<<dim3(8, 32, 8), 128, SMEM_BYTES>>>(Z);
}

// round 12
// speedup vs baseline: 1.5672x; 1.5549x over previous
#include <cuda_runtime.h>
#include <cuda_fp16.h>
#include <stdint.h>

// ============================================================================
// LightAttention via mma.sync m16n8k16 FP16 (f32 accum). fp16 has the SAME
// mantissa precision as tf32 (10 explicit bits) at half the bytes and k16 per
// instruction (vs k8) -> 2x tensor rate, 2x less smem/DRAM traffic.
// 128x128 CTA tiles, 8 warps (2Mx4N, warp 64x32), 2 CTAs/SM, 2-stage cp.async.
//   xconv : x fp32 -> fp16 (RNE)
//   wt    : W [in,out] -> WT [out,in] fp16
//   projq : eQ[n,d]=exp((xq@Wq+b)*s) fp16 (+col-sum partials)
//   projkv: eKT[d,n]=exp((xk@Wk+b)^T*s) fp16 (+row sums); VT[e,n]=(xv@Wv+b)^T
//   combine_sums; bm_split (split-K x4, fp32 partials);
//   bm_combine: BmT[e,d] = (sum)/(ks*qs) * 2^15 -> fp16  (avoids fp16
//               subnormal underflow; z epilogue multiplies by 2^-15, exact)
//   z_gemm: Z = (eQ @ BmT^T) * 2^-15 -> fp32 out.
// Softmax max dropped (exp args in [-0.75,0.75]; max cancels algebraically).
// ============================================================================

#define B_SZ   8
#define N_SEQ  4096
#define DM     512
#define M_ALL  (B_SZ * N_SEQ)
#define ELTS   ((size_t)M_ALL * DM)

static __device__ __constant__ float kINVS = 0.21022410381342863f; // 512^-0.25
#define ZSCALE 0.000030517578125f   // 2^-15
#define BSCALE 32768.0f             // 2^15

// ---------------- scratch ----------------
__device__ __align__(16) __half g_Wt[3 * DM * DM];
__device__ __align__(16) __half g_xh[3 * ELTS];
__device__ __align__(16) __half g_eQ[ELTS];
__device__ __align__(16) __half g_eKT[ELTS];
__device__ __align__(16) __half g_VT[ELTS];
__device__ __align__(16) __half g_BmT[B_SZ * DM * DM];
__device__ __align__(16) float g_BmP[4 * B_SZ * DM * DM];
__device__ float g_pq[256 * DM];
__device__ float g_pk[256 * DM];
__device__ float g_sum[2 * B_SZ * DM];

// ---------------- helpers ----------------
__device__ __forceinline__ uint32_t smem_u32(const void* p) {
    uint32_t r;
    asm("{ .reg .u64 t; cvta.to.shared.u64 t, %1; cvt.u32.u64 %0, t; }" : "=r"(r) : "l"(p));
    return r;
}
__device__ __forceinline__ void ldmx4(uint32_t r[4], uint32_t addr) {
    asm volatile("ldmatrix.sync.aligned.m8n8.x4.shared.b16 {%0,%1,%2,%3}, [%4];"
                 : "=r"(r[0]), "=r"(r[1]), "=r"(r[2]), "=r"(r[3]) : "r"(addr));
}
__device__ __forceinline__ void mma16816(float c[4], const uint32_t a[4], const uint32_t b[2]) {
    asm volatile("mma.sync.aligned.m16n8k16.row.col.f32.f16.f16.f32 "
                 "{%0,%1,%2,%3}, {%4,%5,%6,%7}, {%8,%9}, {%0,%1,%2,%3};"
                 : "+f"(c[0]), "+f"(c[1]), "+f"(c[2]), "+f"(c[3])
                 : "r"(a[0]), "r"(a[1]), "r"(a[2]), "r"(a[3]), "r"(b[0]), "r"(b[1]));
}

#define PITCH    80             // 32 fp16 (64B) + 16B pad (round-3 proven)
#define MATB     10240          // 128 * 80
#define STAGE_B  20480          // 2 matrices
#define SMEM_BYTES 40960        // 2 stages
#define SPB2     272            // epilogue staging pitch: 128 fp16 + 16B pad
#define SW_OFF   36864

// k32 chunk: A[128,32] @ B[128,32]^T fp16, warps 2Mx4N, warp tile 64x32.
// Fragment addressing identical to the round-3 bf16 kernel (verified).
__device__ __forceinline__ void gemm_f16(uint32_t aBase, uint32_t bBase,
                                         int wm, int wn, int lane, float acc[4][4][4]) {
    const int arow = wm * 64 + (lane & 15);
    const uint32_t acolb = (uint32_t)((lane >> 4) * 16);   // (lane>>4)*8 elts * 2B
    const int grp = lane >> 3;
    const int brow = wn * 32 + ((grp >> 1) << 3) + (lane & 7);
    const uint32_t bcolb = (uint32_t)((grp & 1) * 16);
#pragma unroll
    for (int ks = 0; ks < 2; ++ks) {
        const uint32_t kkb = (uint32_t)(ks * 32);          // 16 elts * 2B
        uint32_t a[4][4], b[4][2];
#pragma unroll
        for (int mt = 0; mt < 4; ++mt)
            ldmx4(a[mt], aBase + (uint32_t)(arow + mt * 16) * PITCH + acolb + kkb);
#pragma unroll
        for (int half = 0; half < 2; ++half) {
            uint32_t r[4];
            ldmx4(r, bBase + (uint32_t)(brow + half * 16) * PITCH + bcolb + kkb);
            b[half * 2][0] = r[0]; b[half * 2][1] = r[1];
            b[half * 2 + 1][0] = r[2]; b[half * 2 + 1][1] = r[3];
        }
#pragma unroll
        for (int mt = 0; mt < 4; ++mt)
#pragma unroll
            for (int nt = 0; nt < 4; ++nt)
                mma16816(acc[mt][nt], a[mt], b[nt]);
    }
}

// ---------------- async stage loader (2 fp16 matrices, 128 rows x 64B) -------
__device__ __forceinline__ void load2h(uint32_t smbase, int s,
                                       const __half* aP, int as,
                                       const __half* bP, int bs, int kc, int tid) {
    const uint32_t base = smbase + s * STAGE_B;
#pragma unroll
    for (int i = 0; i < 2; ++i) {
        const int idx = tid + i * 256, row = idx >> 2, c16 = idx & 3;
        const uint32_t d = base + row * PITCH + c16 * 16;
        const __half* g = aP + (size_t)row * as + kc + c16 * 8;
        asm volatile("cp.async.cg.shared.global [%0], [%1], 16;" :: "r"(d), "l"(g));
    }
#pragma unroll
    for (int i = 0; i < 2; ++i) {
        const int idx = tid + i * 256, row = idx >> 2, c16 = idx & 3;
        const uint32_t d = base + MATB + row * PITCH + c16 * 16;
        const __half* g = bP + (size_t)row * bs + kc + c16 * 8;
        asm volatile("cp.async.cg.shared.global [%0], [%1], 16;" :: "r"(d), "l"(g));
    }
    asm volatile("cp.async.commit_group;");
}

// 2-stage mainloop over NCH chunks of K=32 starting at k0.
template<int NCH>
__device__ __forceinline__ void mainloop2(uint32_t smbase,
                                          const __half* aP, int as,
                                          const __half* bP, int bs, int k0,
                                          int tid, int wm, int wn, int lane,
                                          float acc[4][4][4]) {
    load2h(smbase, 0, aP, as, bP, bs, k0, tid);
#pragma unroll 1
    for (int c = 0; c < NCH; ++c) {
        const int s = c & 1;
        asm volatile("cp.async.wait_group 0;" ::: "memory");
        __syncthreads();
        if (c + 1 < NCH) load2h(smbase, 1 - s, aP, as, bP, bs, k0 + (c + 1) * 32, tid);
        gemm_f16(smbase + s * STAGE_B, smbase + s * STAGE_B + MATB, wm, wn, lane, acc);
    }
}

// ---------------- unified projection: grid (4, 256, 3) ----------------
// mz0: A=x B=W, out eQ[n,d]+col sums. mz1: A=W B=x, out eKT[d,n]+row sums.
// mz2: A=W B=x, out VT[e,n].
__global__ __launch_bounds__(256, 2)
void proj_all_kernel(const float* __restrict__ bq, const float* __restrict__ bk,
                     const float* __restrict__ bvv) {
    extern __shared__ char smx[];
    const uint32_t smbase = smem_u32(smx);
    const int tid = threadIdx.x, wid = tid >> 5, lane = tid & 31;
    const int wm = wid & 1, wn = wid >> 1;
    const int bx = blockIdx.x, byr = blockIdx.y, mz = blockIdx.z;
    const bool isQ = (mz == 0);

    const float* bias = (mz == 0) ? bq : (mz == 1) ? bk : bvv;
    const __half* Xh = g_xh + (size_t)mz * ELTS;
    const __half* Wp = g_Wt + (size_t)mz * DM * DM;

    int b = 0, ntile = 0, dtile = 0;
    size_t xRow0, wRow0;
    if (isQ) { xRow0 = (size_t)byr * 128; wRow0 = (size_t)bx * 128; }
    else {
        b = byr >> 5; ntile = byr & 31; dtile = bx;
        xRow0 = (size_t)b * 4096 + (size_t)ntile * 128;
        wRow0 = (size_t)dtile * 128;
    }
    const __half* xP = Xh + xRow0 * 512;
    const __half* wP = Wp + wRow0 * 512;

    float acc[4][4][4];
#pragma unroll
    for (int a = 0; a < 4; ++a)
#pragma unroll
        for (int b2 = 0; b2 < 4; ++b2)
#pragma unroll
            for (int c = 0; c < 4; ++c) acc[a][b2][c] = 0.f;

    if (isQ) mainloop2<16>(smbase, xP, 512, wP, 512, 0, tid, wm, wn, lane, acc);
    else     mainloop2<16>(smbase, wP, 512, xP, 512, 0, tid, wm, wn, lane, acc);
    __syncthreads();

    // ---------------- fused epilogue ----------------
    const int r0 = wm * 64 + (lane >> 2);
    const int c0 = wn * 32 + (lane & 3) * 2;

    float bcol[4][2], brow[4][2];
    if (isQ) {
#pragma unroll
        for (int nt = 0; nt < 4; ++nt) {
            const int cc = bx * 128 + c0 + nt * 8;
            bcol[nt][0] = bias[cc]; bcol[nt][1] = bias[cc + 1];
        }
    } else {
#pragma unroll
        for (int mt = 0; mt < 4; ++mt)
#pragma unroll
            for (int p = 0; p < 2; ++p)
                brow[mt][p] = bias[dtile * 128 + r0 + mt * 16 + p * 8];
    }

    float ps[4][2];
#pragma unroll
    for (int a = 0; a < 4; ++a) { ps[a][0] = 0.f; ps[a][1] = 0.f; }

    char* st = smx;
#pragma unroll
    for (int mt = 0; mt < 4; ++mt)
#pragma unroll
        for (int nt = 0; nt < 4; ++nt)
#pragma unroll
            for (int p = 0; p < 2; ++p) {
                float v0 = acc[mt][nt][p * 2], v1 = acc[mt][nt][p * 2 + 1];
                if (isQ) { v0 += bcol[nt][0]; v1 += bcol[nt][1]; }
                else     { v0 += brow[mt][p]; v1 += brow[mt][p]; }
                if (mz != 2) {
                    v0 = __expf(v0 * kINVS);
                    v1 = __expf(v1 * kINVS);
                }
                const __half h0 = __float2half_rn(v0);
                const __half h1 = __float2half_rn(v1);
                const float q0 = __half2float(h0), q1 = __half2float(h1);
                if (mz == 0) { ps[nt][0] += q0; ps[nt][1] += q1; }
                if (mz == 1) { ps[mt][p] += q0 + q1; }
                const int row = r0 + mt * 16 + p * 8;
                const int col = c0 + nt * 8;
                __half2 o; o.x = h0; o.y = h1;
                *reinterpret_cast<__half2*>(st + row * SPB2 + col * 2) = o;
            }

    float* sW = reinterpret_cast<float*>(smx + SW_OFF);
    if (mz == 0) {
#pragma unroll
        for (int nt = 0; nt < 4; ++nt)
#pragma unroll
            for (int j = 0; j < 2; ++j) {
                ps[nt][j] += __shfl_xor_sync(0xffffffffu, ps[nt][j], 4);
                ps[nt][j] += __shfl_xor_sync(0xffffffffu, ps[nt][j], 8);
                ps[nt][j] += __shfl_xor_sync(0xffffffffu, ps[nt][j], 16);
            }
        if ((lane >> 2) == 0) {
#pragma unroll
            for (int nt = 0; nt < 4; ++nt)
#pragma unroll
                for (int j = 0; j < 2; ++j)
                    sW[wm * 128 + wn * 32 + nt * 8 + (lane & 3) * 2 + j] = ps[nt][j];
        }
    } else if (mz == 1) {
#pragma unroll
        for (int mt = 0; mt < 4; ++mt)
#pragma unroll
            for (int p = 0; p < 2; ++p) {
                ps[mt][p] += __shfl_xor_sync(0xffffffffu, ps[mt][p], 1);
                ps[mt][p] += __shfl_xor_sync(0xffffffffu, ps[mt][p], 2);
            }
        if ((lane & 3) == 0) {
#pragma unroll
            for (int mt = 0; mt < 4; ++mt)
#pragma unroll
                for (int p = 0; p < 2; ++p)
                    sW[wn * 128 + wm * 64 + mt * 16 + p * 8 + (lane >> 2)] = ps[mt][p];
        }
    }
    __syncthreads();

    __half* outP;
    size_t base, stride;
    if (isQ) {
        outP = g_eQ; stride = 512;
        base = (size_t)byr * 128 * 512 + bx * 128;
    } else {
        outP = (mz == 1) ? g_eKT : g_VT; stride = 4096;
        base = ((size_t)b * 512 + dtile * 128) * 4096 + (size_t)ntile * 128;
    }
#pragma unroll
    for (int it = 0; it < 8; ++it) {
        const int idx = tid + it * 256, row = idx >> 4, seg = idx & 15;
        const float4 v = *reinterpret_cast<const float4*>(st + row * SPB2 + seg * 16);
        *reinterpret_cast<float4*>(
            reinterpret_cast<char*>(outP) + (base + (size_t)row * stride + seg * 8) * 2) = v;
    }
    if (mz == 0 && tid < 128)
        g_pq[(size_t)byr * 512 + bx * 128 + tid] = sW[tid] + sW[128 + tid];
    if (mz == 1 && tid < 128)
        g_pk[((size_t)b * 32 + ntile) * 512 + dtile * 128 + tid] =
            sW[tid] + sW[128 + tid] + sW[256 + tid] + sW[384 + tid];
}

// ---------------- combine sums ----------------
__global__ __launch_bounds__(512)
void combine_sums_kernel() {
    const int i = blockIdx.x * 512 + threadIdx.x;
    const int b = i >> 9, d = i & 511;
    float q = 0.f, k = 0.f;
#pragma unroll
    for (int j = 0; j < 32; ++j) {
        q += g_pq[(b * 32 + j) * 512 + d];
        k += g_pk[(b * 32 + j) * 512 + d];
    }
    g_sum[i] = q;
    g_sum[4096 + i] = k;
}

// ---------------- Bm split-K x4: grid (4, 16, 8) ----------------
__global__ __launch_bounds__(256, 2)
void bm_split_kernel() {
    extern __shared__ char smx[];
    const uint32_t smbase = smem_u32(smx);
    const int tid = threadIdx.x, wid = tid >> 5, lane = tid & 31;
    const int wm = wid & 1, wn = wid >> 1;
    const int bx = blockIdx.x, bz = blockIdx.z;
    const int split = blockIdx.y >> 2, ey = blockIdx.y & 3;
    const int k0 = split * 1024;

    const __half* aP = g_VT + ((size_t)bz * 512 + ey * 128) * 4096;
    const __half* bP = g_eKT + ((size_t)bz * 512 + bx * 128) * 4096;

    float acc[4][4][4];
#pragma unroll
    for (int a = 0; a < 4; ++a)
#pragma unroll
        for (int b2 = 0; b2 < 4; ++b2)
#pragma unroll
            for (int c = 0; c < 4; ++c) acc[a][b2][c] = 0.f;

    mainloop2<32>(smbase, aP, 4096, bP, 4096, k0, tid, wm, wn, lane, acc);

    const int r0 = wm * 64 + (lane >> 2);
    const int c0 = wn * 32 + (lane & 3) * 2;
    float* outP = g_BmP + ((size_t)split * 8 + bz) * DM * DM;
#pragma unroll
    for (int mt = 0; mt < 4; ++mt)
#pragma unroll
        for (int nt = 0; nt < 4; ++nt)
#pragma unroll
            for (int p = 0; p < 2; ++p) {
                const int e = ey * 128 + r0 + mt * 16 + p * 8;
                const int d = bx * 128 + c0 + nt * 8;
                float2 o;
                o.x = acc[mt][nt][p * 2];
                o.y = acc[mt][nt][p * 2 + 1];
                *reinterpret_cast<float2*>(outP + (size_t)e * DM + d) = o;
            }
}

// ---------------- Bm combine: sum, scale by 2^15/(ks*qs), fp16 ----------------
__global__ __launch_bounds__(256)
void bm_combine_kernel() {
    const size_t idx = (size_t)blockIdx.x * 256 + threadIdx.x;
    const size_t e4 = idx * 4;
    const int bz = (int)(e4 >> 18);
    const int d0 = (int)(e4 & 511);
    float4 s = reinterpret_cast<const float4*>(g_BmP)[idx];
#pragma unroll
    for (int sp = 1; sp < 4; ++sp) {
        const float4 t = reinterpret_cast<const float4*>(g_BmP + (size_t)sp * 8 * DM * DM)[idx];
        s.x += t.x; s.y += t.y; s.z += t.z; s.w += t.w;
    }
    const float* sq = g_sum + bz * 512 + d0;
    const float* sk = g_sum + 4096 + bz * 512 + d0;
    __half2 lo, hi;
    lo.x = __float2half_rn(s.x * BSCALE / (sk[0] * sq[0]));
    lo.y = __float2half_rn(s.y * BSCALE / (sk[1] * sq[1]));
    hi.x = __float2half_rn(s.z * BSCALE / (sk[2] * sq[2]));
    hi.y = __float2half_rn(s.w * BSCALE / (sk[3] * sq[3]));
    reinterpret_cast<__half2*>(g_BmT)[idx * 2] = lo;
    reinterpret_cast<__half2*>(g_BmT)[idx * 2 + 1] = hi;
}

// ---------------- Z GEMM: grid (4, 32, 8), out = acc * 2^-15 ----------------
__global__ __launch_bounds__(256, 2)
void z_gemm_kernel(float* __restrict__ Z) {
    extern __shared__ char smx[];
    const uint32_t smbase = smem_u32(smx);
    const int tid = threadIdx.x, wid = tid >> 5, lane = tid & 31;
    const int wm = wid & 1, wn = wid >> 1;
    const int bx = blockIdx.x, by = blockIdx.y, bz = blockIdx.z;

    const __half* aP = g_eQ + ((size_t)bz * 4096 + by * 128) * 512;
    const __half* bP = g_BmT + ((size_t)bz * 512 + bx * 128) * 512;

    float acc[4][4][4];
#pragma unroll
    for (int a = 0; a < 4; ++a)
#pragma unroll
        for (int b2 = 0; b2 < 4; ++b2)
#pragma unroll
            for (int c = 0; c < 4; ++c) acc[a][b2][c] = 0.f;

    mainloop2<16>(smbase, aP, 512, bP, 512, 0, tid, wm, wn, lane, acc);

    const int r0 = wm * 64 + (lane >> 2);
    const int c0 = wn * 32 + (lane & 3) * 2;
#pragma unroll
    for (int mt = 0; mt < 4; ++mt)
#pragma unroll
        for (int nt = 0; nt < 4; ++nt)
#pragma unroll
            for (int p = 0; p < 2; ++p) {
                const int cc = bx * 128 + c0 + nt * 8;
                const size_t row = (size_t)bz * 4096 + by * 128 + r0 + mt * 16 + p * 8;
                float2 o;
                o.x = acc[mt][nt][p * 2] * ZSCALE;
                o.y = acc[mt][nt][p * 2 + 1] * ZSCALE;
                *reinterpret_cast<float2*>(Z + row * 512 + cc) = o;
            }
}

// ---------------- x fp32 -> fp16 ----------------
__global__ __launch_bounds__(256)
void xconv_kernel(const float* __restrict__ x0, const float* __restrict__ x1,
                  const float* __restrict__ x2) {
    const int mz = blockIdx.y;
    const float* src = (mz == 0) ? x0 : (mz == 1) ? x1 : x2;
    __half* dst = g_xh + (size_t)mz * ELTS;
    const size_t i = (size_t)blockIdx.x * 256 + threadIdx.x;   // 8-elt index
    const float4 a = reinterpret_cast<const float4*>(src)[i * 2];
    const float4 b = reinterpret_cast<const float4*>(src)[i * 2 + 1];
    __half2 h[4];
    h[0].x = __float2half_rn(a.x); h[0].y = __float2half_rn(a.y);
    h[1].x = __float2half_rn(a.z); h[1].y = __float2half_rn(a.w);
    h[2].x = __float2half_rn(b.x); h[2].y = __float2half_rn(b.y);
    h[3].x = __float2half_rn(b.z); h[3].y = __float2half_rn(b.w);
    reinterpret_cast<float4*>(dst)[i] = *reinterpret_cast<const float4*>(h);
}

// ---------------- weight transpose + fp16 ----------------
__global__ __launch_bounds__(256)
void wt_kernel(const float* __restrict__ w0, const float* __restrict__ w1,
               const float* __restrict__ w2) {
    __shared__ float t[32][33];
    const int mz = blockIdx.z;
    const float* src = (mz == 0) ? w0 : (mz == 1) ? w1 : w2;
    __half* dst = g_Wt + (size_t)mz * DM * DM;
    const int c0 = blockIdx.x * 32, r0 = blockIdx.y * 32;
#pragma unroll
    for (int i = 0; i < 4; ++i) {
        const int r = r0 + threadIdx.y + i * 8;
        t[threadIdx.y + i * 8][threadIdx.x] = src[(size_t)r * DM + c0 + threadIdx.x];
    }
    __syncthreads();
#pragma unroll
    for (int i = 0; i < 4; ++i) {
        const int c = c0 + threadIdx.y + i * 8;
        const int r = r0 + threadIdx.x;
        dst[(size_t)c * DM + r] = __float2half_rn(t[threadIdx.x][threadIdx.y + i * 8]);
    }
}

// ---------------- launch ----------------
extern "C" void kernel_launch(void* const* d_in, const int* in_sizes, int n_in,
                              void* d_out, int out_size) {
    const float* x_q = (const float*)d_in[0];
    const float* x_k = (const float*)d_in[1];
    const float* x_v = (const float*)d_in[2];
    const float* W_q = (const float*)d_in[3];
    const float* b_q = (const float*)d_in[4];
    const float* W_k = (const float*)d_in[5];
    const float* b_k = (const float*)d_in[6];
    const float* W_v = (const float*)d_in[7];
    const float* b_v = (const float*)d_in[8];
    float* Z = (float*)d_out;

    cudaFuncSetAttribute(proj_all_kernel, cudaFuncAttributeMaxDynamicSharedMemorySize, SMEM_BYTES);
    cudaFuncSetAttribute(bm_split_kernel, cudaFuncAttributeMaxDynamicSharedMemorySize, SMEM_BYTES);
    cudaFuncSetAttribute(z_gemm_kernel, cudaFuncAttributeMaxDynamicSharedMemorySize, SMEM_BYTES);

    wt_kernel<<<dim3(16, 16, 3), dim3(32, 8)>>>(W_q, W_k, W_v);
    xconv_kernel<<<dim3((int)(ELTS / 8 / 256), 3), 256>>>(x_q, x_k, x_v);

    proj_all_kernel<<<dim3(4, 256, 3), 256, SMEM_BYTES>>>(b_q, b_k, b_v);

    combine_sums_kernel<<<8, 512>>>();

    bm_split_kernel<<<dim3(4, 16, 8), 256, SMEM_BYTES>>>();
    bm_combine_kernel<<<2048, 256>>>();

    z_gemm_kernel<<<dim3(4, 32, 8), 256, SMEM_BYTES>>>(Z);
}

// round 13
// speedup vs baseline: 1.8312x; 1.1685x over previous
#include <cuda_runtime.h>
#include <cuda_fp16.h>
#include <stdint.h>

// ============================================================================
// LightAttention via mma.sync m16n8k16 FP16 (f32 accum), K-chunk 64.
// 128x128 CTA tiles, 8 warps (2Mx4N, warp 64x32), 2 CTAs/SM, 2-stage cp.async.
//   xconv : x fp32 -> fp16 (RNE);  wt: W [in,out] -> WT [out,in] fp16
//   proj  : mz0 eQ[n,d]=exp((xq@Wq+b)*s) (+col sums)
//           mz1 eKT[d,n]=exp((xk@Wk+b)^T*s) (+row sums)  mz2 VT[e,n]
//   combine_sums; bm_split (split-K x4, fp32 partials);
//   bm_combine: BmT = (sum)/(ks*qs) * 2^15 -> fp16 (subnormal guard)
//   z_gemm: Z = (eQ @ BmT^T) * 2^-15.
// Softmax max dropped (exp args in [-0.75,0.75]; cancels algebraically).
// fp16 mantissa == tf32 mantissa (10 bits) -> same accuracy class, 2x rate.
// ============================================================================

#define B_SZ   8
#define N_SEQ  4096
#define DM     512
#define M_ALL  (B_SZ * N_SEQ)
#define ELTS   ((size_t)M_ALL * DM)

static __device__ __constant__ float kINVS = 0.21022410381342863f; // 512^-0.25
#define ZSCALE 0.000030517578125f   // 2^-15
#define BSCALE 32768.0f             // 2^15

// ---------------- scratch ----------------
__device__ __align__(16) __half g_Wt[3 * DM * DM];
__device__ __align__(16) __half g_xh[3 * ELTS];
__device__ __align__(16) __half g_eQ[ELTS];
__device__ __align__(16) __half g_eKT[ELTS];
__device__ __align__(16) __half g_VT[ELTS];
__device__ __align__(16) __half g_BmT[B_SZ * DM * DM];
__device__ __align__(16) float g_BmP[4 * B_SZ * DM * DM];
__device__ float g_pq[256 * DM];
__device__ float g_pk[256 * DM];
__device__ float g_sum[2 * B_SZ * DM];

// ---------------- helpers ----------------
__device__ __forceinline__ uint32_t smem_u32(const void* p) {
    uint32_t r;
    asm("{ .reg .u64 t; cvta.to.shared.u64 t, %1; cvt.u32.u64 %0, t; }" : "=r"(r) : "l"(p));
    return r;
}
__device__ __forceinline__ void ldmx4(uint32_t r[4], uint32_t addr) {
    asm volatile("ldmatrix.sync.aligned.m8n8.x4.shared.b16 {%0,%1,%2,%3}, [%4];"
                 : "=r"(r[0]), "=r"(r[1]), "=r"(r[2]), "=r"(r[3]) : "r"(addr));
}
__device__ __forceinline__ void mma16816(float c[4], const uint32_t a[4], const uint32_t b[2]) {
    asm volatile("mma.sync.aligned.m16n8k16.row.col.f32.f16.f16.f32 "
                 "{%0,%1,%2,%3}, {%4,%5,%6,%7}, {%8,%9}, {%0,%1,%2,%3};"
                 : "+f"(c[0]), "+f"(c[1]), "+f"(c[2]), "+f"(c[3])
                 : "r"(a[0]), "r"(a[1]), "r"(a[2]), "r"(a[3]), "r"(b[0]), "r"(b[1]));
}

#define PITCH    144            // 64 fp16 (128B) + 16B pad; conflict-free
#define MATB     18432          // 128 * 144
#define STAGE_B  36864          // 2 matrices
#define SMEM_BYTES 73728        // 2 stages
#define SPB2     272            // epilogue staging pitch: 128 fp16 + 16B pad
#define SW_OFF   36864

// k64 chunk: A[128,64] @ B[128,64]^T fp16, warps 2Mx4N, warp tile 64x32.
__device__ __forceinline__ void gemm_f16(uint32_t aBase, uint32_t bBase,
                                         int wm, int wn, int lane, float acc[4][4][4]) {
    const int arow = wm * 64 + (lane & 15);
    const uint32_t acolb = (uint32_t)((lane >> 4) * 16);
    const int grp = lane >> 3;
    const int brow = wn * 32 + ((grp >> 1) << 3) + (lane & 7);
    const uint32_t bcolb = (uint32_t)((grp & 1) * 16);
#pragma unroll
    for (int ks = 0; ks < 4; ++ks) {
        const uint32_t kkb = (uint32_t)(ks * 32);          // 16 elts * 2B
        uint32_t a[4][4], b[4][2];
#pragma unroll
        for (int mt = 0; mt < 4; ++mt)
            ldmx4(a[mt], aBase + (uint32_t)(arow + mt * 16) * PITCH + acolb + kkb);
#pragma unroll
        for (int half = 0; half < 2; ++half) {
            uint32_t r[4];
            ldmx4(r, bBase + (uint32_t)(brow + half * 16) * PITCH + bcolb + kkb);
            b[half * 2][0] = r[0]; b[half * 2][1] = r[1];
            b[half * 2 + 1][0] = r[2]; b[half * 2 + 1][1] = r[3];
        }
#pragma unroll
        for (int mt = 0; mt < 4; ++mt)
#pragma unroll
            for (int nt = 0; nt < 4; ++nt)
                mma16816(acc[mt][nt], a[mt], b[nt]);
    }
}

// ---------------- async stage loader (2 fp16 matrices, 128 rows x 128B) ------
__device__ __forceinline__ void load2h(uint32_t smbase, int s,
                                       const __half* aP, int as,
                                       const __half* bP, int bs, int kc, int tid) {
    const uint32_t base = smbase + s * STAGE_B;
#pragma unroll
    for (int i = 0; i < 4; ++i) {
        const int idx = tid + i * 256, row = idx >> 3, c16 = idx & 7;
        const uint32_t d = base + row * PITCH + c16 * 16;
        const __half* g = aP + (size_t)row * as + kc + c16 * 8;
        asm volatile("cp.async.cg.shared.global [%0], [%1], 16;" :: "r"(d), "l"(g));
    }
#pragma unroll
    for (int i = 0; i < 4; ++i) {
        const int idx = tid + i * 256, row = idx >> 3, c16 = idx & 7;
        const uint32_t d = base + MATB + row * PITCH + c16 * 16;
        const __half* g = bP + (size_t)row * bs + kc + c16 * 8;
        asm volatile("cp.async.cg.shared.global [%0], [%1], 16;" :: "r"(d), "l"(g));
    }
    asm volatile("cp.async.commit_group;");
}

// 2-stage mainloop over NCH chunks of K=64 starting at k0.
template<int NCH>
__device__ __forceinline__ void mainloop2(uint32_t smbase,
                                          const __half* aP, int as,
                                          const __half* bP, int bs, int k0,
                                          int tid, int wm, int wn, int lane,
                                          float acc[4][4][4]) {
    load2h(smbase, 0, aP, as, bP, bs, k0, tid);
#pragma unroll 1
    for (int c = 0; c < NCH; ++c) {
        const int s = c & 1;
        asm volatile("cp.async.wait_group 0;" ::: "memory");
        __syncthreads();
        if (c + 1 < NCH) load2h(smbase, 1 - s, aP, as, bP, bs, k0 + (c + 1) * 64, tid);
        gemm_f16(smbase + s * STAGE_B, smbase + s * STAGE_B + MATB, wm, wn, lane, acc);
    }
}

// ---------------- unified projection: grid (4, 256, 3) ----------------
__global__ __launch_bounds__(256, 2)
void proj_all_kernel(const float* __restrict__ bq, const float* __restrict__ bk,
                     const float* __restrict__ bvv) {
    extern __shared__ char smx[];
    const uint32_t smbase = smem_u32(smx);
    const int tid = threadIdx.x, wid = tid >> 5, lane = tid & 31;
    const int wm = wid & 1, wn = wid >> 1;
    const int bx = blockIdx.x, byr = blockIdx.y, mz = blockIdx.z;
    const bool isQ = (mz == 0);

    const float* bias = (mz == 0) ? bq : (mz == 1) ? bk : bvv;
    const __half* Xh = g_xh + (size_t)mz * ELTS;
    const __half* Wp = g_Wt + (size_t)mz * DM * DM;

    int b = 0, ntile = 0, dtile = 0;
    size_t xRow0, wRow0;
    if (isQ) { xRow0 = (size_t)byr * 128; wRow0 = (size_t)bx * 128; }
    else {
        b = byr >> 5; ntile = byr & 31; dtile = bx;
        xRow0 = (size_t)b * 4096 + (size_t)ntile * 128;
        wRow0 = (size_t)dtile * 128;
    }
    const __half* xP = Xh + xRow0 * 512;
    const __half* wP = Wp + wRow0 * 512;

    float acc[4][4][4];
#pragma unroll
    for (int a = 0; a < 4; ++a)
#pragma unroll
        for (int b2 = 0; b2 < 4; ++b2)
#pragma unroll
            for (int c = 0; c < 4; ++c) acc[a][b2][c] = 0.f;

    if (isQ) mainloop2<8>(smbase, xP, 512, wP, 512, 0, tid, wm, wn, lane, acc);
    else     mainloop2<8>(smbase, wP, 512, xP, 512, 0, tid, wm, wn, lane, acc);
    __syncthreads();

    // ---------------- fused epilogue ----------------
    const int r0 = wm * 64 + (lane >> 2);
    const int c0 = wn * 32 + (lane & 3) * 2;

    float bcol[4][2], brow[4][2];
    if (isQ) {
#pragma unroll
        for (int nt = 0; nt < 4; ++nt) {
            const int cc = bx * 128 + c0 + nt * 8;
            bcol[nt][0] = bias[cc]; bcol[nt][1] = bias[cc + 1];
        }
    } else {
#pragma unroll
        for (int mt = 0; mt < 4; ++mt)
#pragma unroll
            for (int p = 0; p < 2; ++p)
                brow[mt][p] = bias[dtile * 128 + r0 + mt * 16 + p * 8];
    }

    float ps[4][2];
#pragma unroll
    for (int a = 0; a < 4; ++a) { ps[a][0] = 0.f; ps[a][1] = 0.f; }

    char* st = smx;
#pragma unroll
    for (int mt = 0; mt < 4; ++mt)
#pragma unroll
        for (int nt = 0; nt < 4; ++nt)
#pragma unroll
            for (int p = 0; p < 2; ++p) {
                float v0 = acc[mt][nt][p * 2], v1 = acc[mt][nt][p * 2 + 1];
                if (isQ) { v0 += bcol[nt][0]; v1 += bcol[nt][1]; }
                else     { v0 += brow[mt][p]; v1 += brow[mt][p]; }
                if (mz != 2) {
                    v0 = __expf(v0 * kINVS);
                    v1 = __expf(v1 * kINVS);
                }
                const __half h0 = __float2half_rn(v0);
                const __half h1 = __float2half_rn(v1);
                const float q0 = __half2float(h0), q1 = __half2float(h1);
                if (mz == 0) { ps[nt][0] += q0; ps[nt][1] += q1; }
                if (mz == 1) { ps[mt][p] += q0 + q1; }
                const int row = r0 + mt * 16 + p * 8;
                const int col = c0 + nt * 8;
                __half2 o; o.x = h0; o.y = h1;
                *reinterpret_cast<__half2*>(st + row * SPB2 + col * 2) = o;
            }

    float* sW = reinterpret_cast<float*>(smx + SW_OFF);
    if (mz == 0) {
#pragma unroll
        for (int nt = 0; nt < 4; ++nt)
#pragma unroll
            for (int j = 0; j < 2; ++j) {
                ps[nt][j] += __shfl_xor_sync(0xffffffffu, ps[nt][j], 4);
                ps[nt][j] += __shfl_xor_sync(0xffffffffu, ps[nt][j], 8);
                ps[nt][j] += __shfl_xor_sync(0xffffffffu, ps[nt][j], 16);
            }
        if ((lane >> 2) == 0) {
#pragma unroll
            for (int nt = 0; nt < 4; ++nt)
#pragma unroll
                for (int j = 0; j < 2; ++j)
                    sW[wm * 128 + wn * 32 + nt * 8 + (lane & 3) * 2 + j] = ps[nt][j];
        }
    } else if (mz == 1) {
#pragma unroll
        for (int mt = 0; mt < 4; ++mt)
#pragma unroll
            for (int p = 0; p < 2; ++p) {
                ps[mt][p] += __shfl_xor_sync(0xffffffffu, ps[mt][p], 1);
                ps[mt][p] += __shfl_xor_sync(0xffffffffu, ps[mt][p], 2);
            }
        if ((lane & 3) == 0) {
#pragma unroll
            for (int mt = 0; mt < 4; ++mt)
#pragma unroll
                for (int p = 0; p < 2; ++p)
                    sW[wn * 128 + wm * 64 + mt * 16 + p * 8 + (lane >> 2)] = ps[mt][p];
        }
    }
    __syncthreads();

    __half* outP;
    size_t base, stride;
    if (isQ) {
        outP = g_eQ; stride = 512;
        base = (size_t)byr * 128 * 512 + bx * 128;
    } else {
        outP = (mz == 1) ? g_eKT : g_VT; stride = 4096;
        base = ((size_t)b * 512 + dtile * 128) * 4096 + (size_t)ntile * 128;
    }
#pragma unroll
    for (int it = 0; it < 8; ++it) {
        const int idx = tid + it * 256, row = idx >> 4, seg = idx & 15;
        const float4 v = *reinterpret_cast<const float4*>(st + row * SPB2 + seg * 16);
        *reinterpret_cast<float4*>(
            reinterpret_cast<char*>(outP) + (base + (size_t)row * stride + seg * 8) * 2) = v;
    }
    if (mz == 0 && tid < 128)
        g_pq[(size_t)byr * 512 + bx * 128 + tid] = sW[tid] + sW[128 + tid];
    if (mz == 1 && tid < 128)
        g_pk[((size_t)b * 32 + ntile) * 512 + dtile * 128 + tid] =
            sW[tid] + sW[128 + tid] + sW[256 + tid] + sW[384 + tid];
}

// ---------------- combine sums ----------------
__global__ __launch_bounds__(512)
void combine_sums_kernel() {
    const int i = blockIdx.x * 512 + threadIdx.x;
    const int b = i >> 9, d = i & 511;
    float q = 0.f, k = 0.f;
#pragma unroll
    for (int j = 0; j < 32; ++j) {
        q += g_pq[(b * 32 + j) * 512 + d];
        k += g_pk[(b * 32 + j) * 512 + d];
    }
    g_sum[i] = q;
    g_sum[4096 + i] = k;
}

// ---------------- Bm split-K x4: grid (4, 16, 8) ----------------
__global__ __launch_bounds__(256, 2)
void bm_split_kernel() {
    extern __shared__ char smx[];
    const uint32_t smbase = smem_u32(smx);
    const int tid = threadIdx.x, wid = tid >> 5, lane = tid & 31;
    const int wm = wid & 1, wn = wid >> 1;
    const int bx = blockIdx.x, bz = blockIdx.z;
    const int split = blockIdx.y >> 2, ey = blockIdx.y & 3;
    const int k0 = split * 1024;

    const __half* aP = g_VT + ((size_t)bz * 512 + ey * 128) * 4096;
    const __half* bP = g_eKT + ((size_t)bz * 512 + bx * 128) * 4096;

    float acc[4][4][4];
#pragma unroll
    for (int a = 0; a < 4; ++a)
#pragma unroll
        for (int b2 = 0; b2 < 4; ++b2)
#pragma unroll
            for (int c = 0; c < 4; ++c) acc[a][b2][c] = 0.f;

    mainloop2<16>(smbase, aP, 4096, bP, 4096, k0, tid, wm, wn, lane, acc);

    const int r0 = wm * 64 + (lane >> 2);
    const int c0 = wn * 32 + (lane & 3) * 2;
    float* outP = g_BmP + ((size_t)split * 8 + bz) * DM * DM;
#pragma unroll
    for (int mt = 0; mt < 4; ++mt)
#pragma unroll
        for (int nt = 0; nt < 4; ++nt)
#pragma unroll
            for (int p = 0; p < 2; ++p) {
                const int e = ey * 128 + r0 + mt * 16 + p * 8;
                const int d = bx * 128 + c0 + nt * 8;
                float2 o;
                o.x = acc[mt][nt][p * 2];
                o.y = acc[mt][nt][p * 2 + 1];
                *reinterpret_cast<float2*>(outP + (size_t)e * DM + d) = o;
            }
}

// ---------------- Bm combine: sum, scale by 2^15/(ks*qs), fp16 ----------------
__global__ __launch_bounds__(256)
void bm_combine_kernel() {
    const size_t idx = (size_t)blockIdx.x * 256 + threadIdx.x;
    const size_t e4 = idx * 4;
    const int bz = (int)(e4 >> 18);
    const int d0 = (int)(e4 & 511);
    float4 s = reinterpret_cast<const float4*>(g_BmP)[idx];
#pragma unroll
    for (int sp = 1; sp < 4; ++sp) {
        const float4 t = reinterpret_cast<const float4*>(g_BmP + (size_t)sp * 8 * DM * DM)[idx];
        s.x += t.x; s.y += t.y; s.z += t.z; s.w += t.w;
    }
    const float* sq = g_sum + bz * 512 + d0;
    const float* sk = g_sum + 4096 + bz * 512 + d0;
    __half2 lo, hi;
    lo.x = __float2half_rn(s.x * BSCALE / (sk[0] * sq[0]));
    lo.y = __float2half_rn(s.y * BSCALE / (sk[1] * sq[1]));
    hi.x = __float2half_rn(s.z * BSCALE / (sk[2] * sq[2]));
    hi.y = __float2half_rn(s.w * BSCALE / (sk[3] * sq[3]));
    reinterpret_cast<__half2*>(g_BmT)[idx * 2] = lo;
    reinterpret_cast<__half2*>(g_BmT)[idx * 2 + 1] = hi;
}

// ---------------- Z GEMM: grid (4, 32, 8), out = acc * 2^-15 ----------------
__global__ __launch_bounds__(256, 2)
void z_gemm_kernel(float* __restrict__ Z) {
    extern __shared__ char smx[];
    const uint32_t smbase = smem_u32(smx);
    const int tid = threadIdx.x, wid = tid >> 5, lane = tid & 31;
    const int wm = wid & 1, wn = wid >> 1;
    const int bx = blockIdx.x, by = blockIdx.y, bz = blockIdx.z;

    const __half* aP = g_eQ + ((size_t)bz * 4096 + by * 128) * 512;
    const __half* bP = g_BmT + ((size_t)bz * 512 + bx * 128) * 512;

    float acc[4][4][4];
#pragma unroll
    for (int a = 0; a < 4; ++a)
#pragma unroll
        for (int b2 = 0; b2 < 4; ++b2)
#pragma unroll
            for (int c = 0; c < 4; ++c) acc[a][b2][c] = 0.f;

    mainloop2<8>(smbase, aP, 512, bP, 512, 0, tid, wm, wn, lane, acc);

    const int r0 = wm * 64 + (lane >> 2);
    const int c0 = wn * 32 + (lane & 3) * 2;
#pragma unroll
    for (int mt = 0; mt < 4; ++mt)
#pragma unroll
        for (int nt = 0; nt < 4; ++nt)
#pragma unroll
            for (int p = 0; p < 2; ++p) {
                const int cc = bx * 128 + c0 + nt * 8;
                const size_t row = (size_t)bz * 4096 + by * 128 + r0 + mt * 16 + p * 8;
                float2 o;
                o.x = acc[mt][nt][p * 2] * ZSCALE;
                o.y = acc[mt][nt][p * 2 + 1] * ZSCALE;
                *reinterpret_cast<float2*>(Z + row * 512 + cc) = o;
            }
}

// ---------------- x fp32 -> fp16 ----------------
__global__ __launch_bounds__(256)
void xconv_kernel(const float* __restrict__ x0, const float* __restrict__ x1,
                  const float* __restrict__ x2) {
    const int mz = blockIdx.y;
    const float* src = (mz == 0) ? x0 : (mz == 1) ? x1 : x2;
    __half* dst = g_xh + (size_t)mz * ELTS;
    const size_t i = (size_t)blockIdx.x * 256 + threadIdx.x;
    const float4 a = reinterpret_cast<const float4*>(src)[i * 2];
    const float4 b = reinterpret_cast<const float4*>(src)[i * 2 + 1];
    __half2 h[4];
    h[0].x = __float2half_rn(a.x); h[0].y = __float2half_rn(a.y);
    h[1].x = __float2half_rn(a.z); h[1].y = __float2half_rn(a.w);
    h[2].x = __float2half_rn(b.x); h[2].y = __float2half_rn(b.y);
    h[3].x = __float2half_rn(b.z); h[3].y = __float2half_rn(b.w);
    reinterpret_cast<float4*>(dst)[i] = *reinterpret_cast<const float4*>(h);
}

// ---------------- weight transpose + fp16 ----------------
__global__ __launch_bounds__(256)
void wt_kernel(const float* __restrict__ w0, const float* __restrict__ w1,
               const float* __restrict__ w2) {
    __shared__ float t[32][33];
    const int mz = blockIdx.z;
    const float* src = (mz == 0) ? w0 : (mz == 1) ? w1 : w2;
    __half* dst = g_Wt + (size_t)mz * DM * DM;
    const int c0 = blockIdx.x * 32, r0 = blockIdx.y * 32;
#pragma unroll
    for (int i = 0; i < 4; ++i) {
        const int r = r0 + threadIdx.y + i * 8;
        t[threadIdx.y + i * 8][threadIdx.x] = src[(size_t)r * DM + c0 + threadIdx.x];
    }
    __syncthreads();
#pragma unroll
    for (int i = 0; i < 4; ++i) {
        const int c = c0 + threadIdx.y + i * 8;
        const int r = r0 + threadIdx.x;
        dst[(size_t)c * DM + r] = __float2half_rn(t[threadIdx.x][threadIdx.y + i * 8]);
    }
}

// ---------------- launch ----------------
extern "C" void kernel_launch(void* const* d_in, const int* in_sizes, int n_in,
                              void* d_out, int out_size) {
    const float* x_q = (const float*)d_in[0];
    const float* x_k = (const float*)d_in[1];
    const float* x_v = (const float*)d_in[2];
    const float* W_q = (const float*)d_in[3];
    const float* b_q = (const float*)d_in[4];
    const float* W_k = (const float*)d_in[5];
    const float* b_k = (const float*)d_in[6];
    const float* W_v = (const float*)d_in[7];
    const float* b_v = (const float*)d_in[8];
    float* Z = (float*)d_out;

    cudaFuncSetAttribute(proj_all_kernel, cudaFuncAttributeMaxDynamicSharedMemorySize, SMEM_BYTES);
    cudaFuncSetAttribute(bm_split_kernel, cudaFuncAttributeMaxDynamicSharedMemorySize, SMEM_BYTES);
    cudaFuncSetAttribute(z_gemm_kernel, cudaFuncAttributeMaxDynamicSharedMemorySize, SMEM_BYTES);

    wt_kernel<<<dim3(16, 16, 3), dim3(32, 8)>>>(W_q, W_k, W_v);
    xconv_kernel<<<dim3((int)(ELTS / 8 / 256), 3), 256>>>(x_q, x_k, x_v);

    proj_all_kernel<<<dim3(4, 256, 3), 256, SMEM_BYTES>>>(b_q, b_k, b_v);

    combine_sums_kernel<<<8, 512>>>();

    bm_split_kernel<<<dim3(4, 16, 8), 256, SMEM_BYTES>>>();
    bm_combine_kernel<<<2048, 256>>>();

    z_gemm_kernel<<<dim3(4, 32, 8), 256, SMEM_BYTES>>>(Z);
}

// round 14
// speedup vs baseline: 1.9185x; 1.0477x over previous
#include <cuda_runtime.h>
#include <cuda_fp16.h>
#include <stdint.h>

// ============================================================================
// LightAttention via mma.sync m16n8k16 FP16 (f32 accum), K-chunk 64.
// 128x128 CTA tiles, 8 warps (2Mx4N, warp 64x32), 2 CTAs/SM, 2-stage cp.async.
// Round-13 kernels unchanged; launch graph uses fork/join streams so projQ
// runs concurrently with projKV -> bm_split (independent subgraphs).
//   xconv : x fp32 -> fp16 (RNE);  wt: W [in,out] -> WT [out,in] fp16
//   projKV: eKT[d,n]=exp((xk@Wk+b)^T*s) (+row sums); VT[e,n]=(xv@Wv+b)^T
//   projQ : eQ[n,d]=exp((xq@Wq+b)*s) (+col sums)        [side stream]
//   combine_sums; bm_split (split-K x4, fp32 partials);
//   bm_combine: BmT = (sum)/(ks*qs) * 2^15 -> fp16 (subnormal guard)
//   z_gemm: Z = (eQ @ BmT^T) * 2^-15.
// Softmax max dropped (exp args in [-0.75,0.75]; cancels algebraically).
// ============================================================================

#define B_SZ   8
#define N_SEQ  4096
#define DM     512
#define M_ALL  (B_SZ * N_SEQ)
#define ELTS   ((size_t)M_ALL * DM)

static __device__ __constant__ float kINVS = 0.21022410381342863f; // 512^-0.25
#define ZSCALE 0.000030517578125f   // 2^-15
#define BSCALE 32768.0f             // 2^15

// ---------------- scratch ----------------
__device__ __align__(16) __half g_Wt[3 * DM * DM];
__device__ __align__(16) __half g_xh[3 * ELTS];
__device__ __align__(16) __half g_eQ[ELTS];
__device__ __align__(16) __half g_eKT[ELTS];
__device__ __align__(16) __half g_VT[ELTS];
__device__ __align__(16) __half g_BmT[B_SZ * DM * DM];
__device__ __align__(16) float g_BmP[4 * B_SZ * DM * DM];
__device__ float g_pq[256 * DM];
__device__ float g_pk[256 * DM];
__device__ float g_sum[2 * B_SZ * DM];

// ---------------- helpers ----------------
__device__ __forceinline__ uint32_t smem_u32(const void* p) {
    uint32_t r;
    asm("{ .reg .u64 t; cvta.to.shared.u64 t, %1; cvt.u32.u64 %0, t; }" : "=r"(r) : "l"(p));
    return r;
}
__device__ __forceinline__ void ldmx4(uint32_t r[4], uint32_t addr) {
    asm volatile("ldmatrix.sync.aligned.m8n8.x4.shared.b16 {%0,%1,%2,%3}, [%4];"
                 : "=r"(r[0]), "=r"(r[1]), "=r"(r[2]), "=r"(r[3]) : "r"(addr));
}
__device__ __forceinline__ void mma16816(float c[4], const uint32_t a[4], const uint32_t b[2]) {
    asm volatile("mma.sync.aligned.m16n8k16.row.col.f32.f16.f16.f32 "
                 "{%0,%1,%2,%3}, {%4,%5,%6,%7}, {%8,%9}, {%0,%1,%2,%3};"
                 : "+f"(c[0]), "+f"(c[1]), "+f"(c[2]), "+f"(c[3])
                 : "r"(a[0]), "r"(a[1]), "r"(a[2]), "r"(a[3]), "r"(b[0]), "r"(b[1]));
}

#define PITCH    144            // 64 fp16 (128B) + 16B pad; conflict-free
#define MATB     18432          // 128 * 144
#define STAGE_B  36864          // 2 matrices
#define SMEM_BYTES 73728        // 2 stages
#define SPB2     272            // epilogue staging pitch: 128 fp16 + 16B pad
#define SW_OFF   36864

// k64 chunk: A[128,64] @ B[128,64]^T fp16, warps 2Mx4N, warp tile 64x32.
__device__ __forceinline__ void gemm_f16(uint32_t aBase, uint32_t bBase,
                                         int wm, int wn, int lane, float acc[4][4][4]) {
    const int arow = wm * 64 + (lane & 15);
    const uint32_t acolb = (uint32_t)((lane >> 4) * 16);
    const int grp = lane >> 3;
    const int brow = wn * 32 + ((grp >> 1) << 3) + (lane & 7);
    const uint32_t bcolb = (uint32_t)((grp & 1) * 16);
#pragma unroll
    for (int ks = 0; ks < 4; ++ks) {
        const uint32_t kkb = (uint32_t)(ks * 32);
        uint32_t a[4][4], b[4][2];
#pragma unroll
        for (int mt = 0; mt < 4; ++mt)
            ldmx4(a[mt], aBase + (uint32_t)(arow + mt * 16) * PITCH + acolb + kkb);
#pragma unroll
        for (int half = 0; half < 2; ++half) {
            uint32_t r[4];
            ldmx4(r, bBase + (uint32_t)(brow + half * 16) * PITCH + bcolb + kkb);
            b[half * 2][0] = r[0]; b[half * 2][1] = r[1];
            b[half * 2 + 1][0] = r[2]; b[half * 2 + 1][1] = r[3];
        }
#pragma unroll
        for (int mt = 0; mt < 4; ++mt)
#pragma unroll
            for (int nt = 0; nt < 4; ++nt)
                mma16816(acc[mt][nt], a[mt], b[nt]);
    }
}

// ---------------- async stage loader (2 fp16 matrices, 128 rows x 128B) ------
__device__ __forceinline__ void load2h(uint32_t smbase, int s,
                                       const __half* aP, int as,
                                       const __half* bP, int bs, int kc, int tid) {
    const uint32_t base = smbase + s * STAGE_B;
#pragma unroll
    for (int i = 0; i < 4; ++i) {
        const int idx = tid + i * 256, row = idx >> 3, c16 = idx & 7;
        const uint32_t d = base + row * PITCH + c16 * 16;
        const __half* g = aP + (size_t)row * as + kc + c16 * 8;
        asm volatile("cp.async.cg.shared.global [%0], [%1], 16;" :: "r"(d), "l"(g));
    }
#pragma unroll
    for (int i = 0; i < 4; ++i) {
        const int idx = tid + i * 256, row = idx >> 3, c16 = idx & 7;
        const uint32_t d = base + MATB + row * PITCH + c16 * 16;
        const __half* g = bP + (size_t)row * bs + kc + c16 * 8;
        asm volatile("cp.async.cg.shared.global [%0], [%1], 16;" :: "r"(d), "l"(g));
    }
    asm volatile("cp.async.commit_group;");
}

// 2-stage mainloop over NCH chunks of K=64 starting at k0.
template<int NCH>
__device__ __forceinline__ void mainloop2(uint32_t smbase,
                                          const __half* aP, int as,
                                          const __half* bP, int bs, int k0,
                                          int tid, int wm, int wn, int lane,
                                          float acc[4][4][4]) {
    load2h(smbase, 0, aP, as, bP, bs, k0, tid);
#pragma unroll 1
    for (int c = 0; c < NCH; ++c) {
        const int s = c & 1;
        asm volatile("cp.async.wait_group 0;" ::: "memory");
        __syncthreads();
        if (c + 1 < NCH) load2h(smbase, 1 - s, aP, as, bP, bs, k0 + (c + 1) * 64, tid);
        gemm_f16(smbase + s * STAGE_B, smbase + s * STAGE_B + MATB, wm, wn, lane, acc);
    }
}

// ---------------- unified projection, mz = blockIdx.z + MZB ----------------
// mz0: A=x B=W, out eQ[n,d]+col sums. mz1: A=W B=x, out eKT[d,n]+row sums.
// mz2: A=W B=x, out VT[e,n].
template<int MZB>
__global__ __launch_bounds__(256, 2)
void proj_all_kernel(const float* __restrict__ bq, const float* __restrict__ bk,
                     const float* __restrict__ bvv) {
    extern __shared__ char smx[];
    const uint32_t smbase = smem_u32(smx);
    const int tid = threadIdx.x, wid = tid >> 5, lane = tid & 31;
    const int wm = wid & 1, wn = wid >> 1;
    const int bx = blockIdx.x, byr = blockIdx.y, mz = blockIdx.z + MZB;
    const bool isQ = (mz == 0);

    const float* bias = (mz == 0) ? bq : (mz == 1) ? bk : bvv;
    const __half* Xh = g_xh + (size_t)mz * ELTS;
    const __half* Wp = g_Wt + (size_t)mz * DM * DM;

    int b = 0, ntile = 0, dtile = 0;
    size_t xRow0, wRow0;
    if (isQ) { xRow0 = (size_t)byr * 128; wRow0 = (size_t)bx * 128; }
    else {
        b = byr >> 5; ntile = byr & 31; dtile = bx;
        xRow0 = (size_t)b * 4096 + (size_t)ntile * 128;
        wRow0 = (size_t)dtile * 128;
    }
    const __half* xP = Xh + xRow0 * 512;
    const __half* wP = Wp + wRow0 * 512;

    float acc[4][4][4];
#pragma unroll
    for (int a = 0; a < 4; ++a)
#pragma unroll
        for (int b2 = 0; b2 < 4; ++b2)
#pragma unroll
            for (int c = 0; c < 4; ++c) acc[a][b2][c] = 0.f;

    if (isQ) mainloop2<8>(smbase, xP, 512, wP, 512, 0, tid, wm, wn, lane, acc);
    else     mainloop2<8>(smbase, wP, 512, xP, 512, 0, tid, wm, wn, lane, acc);
    __syncthreads();

    // ---------------- fused epilogue ----------------
    const int r0 = wm * 64 + (lane >> 2);
    const int c0 = wn * 32 + (lane & 3) * 2;

    float bcol[4][2], brow[4][2];
    if (isQ) {
#pragma unroll
        for (int nt = 0; nt < 4; ++nt) {
            const int cc = bx * 128 + c0 + nt * 8;
            bcol[nt][0] = bias[cc]; bcol[nt][1] = bias[cc + 1];
        }
    } else {
#pragma unroll
        for (int mt = 0; mt < 4; ++mt)
#pragma unroll
            for (int p = 0; p < 2; ++p)
                brow[mt][p] = bias[dtile * 128 + r0 + mt * 16 + p * 8];
    }

    float ps[4][2];
#pragma unroll
    for (int a = 0; a < 4; ++a) { ps[a][0] = 0.f; ps[a][1] = 0.f; }

    char* st = smx;
#pragma unroll
    for (int mt = 0; mt < 4; ++mt)
#pragma unroll
        for (int nt = 0; nt < 4; ++nt)
#pragma unroll
            for (int p = 0; p < 2; ++p) {
                float v0 = acc[mt][nt][p * 2], v1 = acc[mt][nt][p * 2 + 1];
                if (isQ) { v0 += bcol[nt][0]; v1 += bcol[nt][1]; }
                else     { v0 += brow[mt][p]; v1 += brow[mt][p]; }
                if (mz != 2) {
                    v0 = __expf(v0 * kINVS);
                    v1 = __expf(v1 * kINVS);
                }
                const __half h0 = __float2half_rn(v0);
                const __half h1 = __float2half_rn(v1);
                const float q0 = __half2float(h0), q1 = __half2float(h1);
                if (mz == 0) { ps[nt][0] += q0; ps[nt][1] += q1; }
                if (mz == 1) { ps[mt][p] += q0 + q1; }
                const int row = r0 + mt * 16 + p * 8;
                const int col = c0 + nt * 8;
                __half2 o; o.x = h0; o.y = h1;
                *reinterpret_cast<__half2*>(st + row * SPB2 + col * 2) = o;
            }

    float* sW = reinterpret_cast<float*>(smx + SW_OFF);
    if (mz == 0) {
#pragma unroll
        for (int nt = 0; nt < 4; ++nt)
#pragma unroll
            for (int j = 0; j < 2; ++j) {
                ps[nt][j] += __shfl_xor_sync(0xffffffffu, ps[nt][j], 4);
                ps[nt][j] += __shfl_xor_sync(0xffffffffu, ps[nt][j], 8);
                ps[nt][j] += __shfl_xor_sync(0xffffffffu, ps[nt][j], 16);
            }
        if ((lane >> 2) == 0) {
#pragma unroll
            for (int nt = 0; nt < 4; ++nt)
#pragma unroll
                for (int j = 0; j < 2; ++j)
                    sW[wm * 128 + wn * 32 + nt * 8 + (lane & 3) * 2 + j] = ps[nt][j];
        }
    } else if (mz == 1) {
#pragma unroll
        for (int mt = 0; mt < 4; ++mt)
#pragma unroll
            for (int p = 0; p < 2; ++p) {
                ps[mt][p] += __shfl_xor_sync(0xffffffffu, ps[mt][p], 1);
                ps[mt][p] += __shfl_xor_sync(0xffffffffu, ps[mt][p], 2);
            }
        if ((lane & 3) == 0) {
#pragma unroll
            for (int mt = 0; mt < 4; ++mt)
#pragma unroll
                for (int p = 0; p < 2; ++p)
                    sW[wn * 128 + wm * 64 + mt * 16 + p * 8 + (lane >> 2)] = ps[mt][p];
        }
    }
    __syncthreads();

    __half* outP;
    size_t base, stride;
    if (isQ) {
        outP = g_eQ; stride = 512;
        base = (size_t)byr * 128 * 512 + bx * 128;
    } else {
        outP = (mz == 1) ? g_eKT : g_VT; stride = 4096;
        base = ((size_t)b * 512 + dtile * 128) * 4096 + (size_t)ntile * 128;
    }
#pragma unroll
    for (int it = 0; it < 8; ++it) {
        const int idx = tid + it * 256, row = idx >> 4, seg = idx & 15;
        const float4 v = *reinterpret_cast<const float4*>(st + row * SPB2 + seg * 16);
        *reinterpret_cast<float4*>(
            reinterpret_cast<char*>(outP) + (base + (size_t)row * stride + seg * 8) * 2) = v;
    }
    if (mz == 0 && tid < 128)
        g_pq[(size_t)byr * 512 + bx * 128 + tid] = sW[tid] + sW[128 + tid];
    if (mz == 1 && tid < 128)
        g_pk[((size_t)b * 32 + ntile) * 512 + dtile * 128 + tid] =
            sW[tid] + sW[128 + tid] + sW[256 + tid] + sW[384 + tid];
}

// ---------------- combine sums ----------------
__global__ __launch_bounds__(512)
void combine_sums_kernel() {
    const int i = blockIdx.x * 512 + threadIdx.x;
    const int b = i >> 9, d = i & 511;
    float q = 0.f, k = 0.f;
#pragma unroll
    for (int j = 0; j < 32; ++j) {
        q += g_pq[(b * 32 + j) * 512 + d];
        k += g_pk[(b * 32 + j) * 512 + d];
    }
    g_sum[i] = q;
    g_sum[4096 + i] = k;
}

// ---------------- Bm split-K x4: grid (4, 16, 8) ----------------
__global__ __launch_bounds__(256, 2)
void bm_split_kernel() {
    extern __shared__ char smx[];
    const uint32_t smbase = smem_u32(smx);
    const int tid = threadIdx.x, wid = tid >> 5, lane = tid & 31;
    const int wm = wid & 1, wn = wid >> 1;
    const int bx = blockIdx.x, bz = blockIdx.z;
    const int split = blockIdx.y >> 2, ey = blockIdx.y & 3;
    const int k0 = split * 1024;

    const __half* aP = g_VT + ((size_t)bz * 512 + ey * 128) * 4096;
    const __half* bP = g_eKT + ((size_t)bz * 512 + bx * 128) * 4096;

    float acc[4][4][4];
#pragma unroll
    for (int a = 0; a < 4; ++a)
#pragma unroll
        for (int b2 = 0; b2 < 4; ++b2)
#pragma unroll
            for (int c = 0; c < 4; ++c) acc[a][b2][c] = 0.f;

    mainloop2<16>(smbase, aP, 4096, bP, 4096, k0, tid, wm, wn, lane, acc);

    const int r0 = wm * 64 + (lane >> 2);
    const int c0 = wn * 32 + (lane & 3) * 2;
    float* outP = g_BmP + ((size_t)split * 8 + bz) * DM * DM;
#pragma unroll
    for (int mt = 0; mt < 4; ++mt)
#pragma unroll
        for (int nt = 0; nt < 4; ++nt)
#pragma unroll
            for (int p = 0; p < 2; ++p) {
                const int e = ey * 128 + r0 + mt * 16 + p * 8;
                const int d = bx * 128 + c0 + nt * 8;
                float2 o;
                o.x = acc[mt][nt][p * 2];
                o.y = acc[mt][nt][p * 2 + 1];
                *reinterpret_cast<float2*>(outP + (size_t)e * DM + d) = o;
            }
}

// ---------------- Bm combine: sum, scale by 2^15/(ks*qs), fp16 ----------------
__global__ __launch_bounds__(256)
void bm_combine_kernel() {
    const size_t idx = (size_t)blockIdx.x * 256 + threadIdx.x;
    const size_t e4 = idx * 4;
    const int bz = (int)(e4 >> 18);
    const int d0 = (int)(e4 & 511);
    float4 s = reinterpret_cast<const float4*>(g_BmP)[idx];
#pragma unroll
    for (int sp = 1; sp < 4; ++sp) {
        const float4 t = reinterpret_cast<const float4*>(g_BmP + (size_t)sp * 8 * DM * DM)[idx];
        s.x += t.x; s.y += t.y; s.z += t.z; s.w += t.w;
    }
    const float* sq = g_sum + bz * 512 + d0;
    const float* sk = g_sum + 4096 + bz * 512 + d0;
    __half2 lo, hi;
    lo.x = __float2half_rn(s.x * BSCALE / (sk[0] * sq[0]));
    lo.y = __float2half_rn(s.y * BSCALE / (sk[1] * sq[1]));
    hi.x = __float2half_rn(s.z * BSCALE / (sk[2] * sq[2]));
    hi.y = __float2half_rn(s.w * BSCALE / (sk[3] * sq[3]));
    reinterpret_cast<__half2*>(g_BmT)[idx * 2] = lo;
    reinterpret_cast<__half2*>(g_BmT)[idx * 2 + 1] = hi;
}

// ---------------- Z GEMM: grid (4, 32, 8), out = acc * 2^-15 ----------------
__global__ __launch_bounds__(256, 2)
void z_gemm_kernel(float* __restrict__ Z) {
    extern __shared__ char smx[];
    const uint32_t smbase = smem_u32(smx);
    const int tid = threadIdx.x, wid = tid >> 5, lane = tid & 31;
    const int wm = wid & 1, wn = wid >> 1;
    const int bx = blockIdx.x, by = blockIdx.y, bz = blockIdx.z;

    const __half* aP = g_eQ + ((size_t)bz * 4096 + by * 128) * 512;
    const __half* bP = g_BmT + ((size_t)bz * 512 + bx * 128) * 512;

    float acc[4][4][4];
#pragma unroll
    for (int a = 0; a < 4; ++a)
#pragma unroll
        for (int b2 = 0; b2 < 4; ++b2)
#pragma unroll
            for (int c = 0; c < 4; ++c) acc[a][b2][c] = 0.f;

    mainloop2<8>(smbase, aP, 512, bP, 512, 0, tid, wm, wn, lane, acc);

    const int r0 = wm * 64 + (lane >> 2);
    const int c0 = wn * 32 + (lane & 3) * 2;
#pragma unroll
    for (int mt = 0; mt < 4; ++mt)
#pragma unroll
        for (int nt = 0; nt < 4; ++nt)
#pragma unroll
            for (int p = 0; p < 2; ++p) {
                const int cc = bx * 128 + c0 + nt * 8;
                const size_t row = (size_t)bz * 4096 + by * 128 + r0 + mt * 16 + p * 8;
                float2 o;
                o.x = acc[mt][nt][p * 2] * ZSCALE;
                o.y = acc[mt][nt][p * 2 + 1] * ZSCALE;
                *reinterpret_cast<float2*>(Z + row * 512 + cc) = o;
            }
}

// ---------------- x fp32 -> fp16 ----------------
__global__ __launch_bounds__(256)
void xconv_kernel(const float* __restrict__ x0, const float* __restrict__ x1,
                  const float* __restrict__ x2) {
    const int mz = blockIdx.y;
    const float* src = (mz == 0) ? x0 : (mz == 1) ? x1 : x2;
    __half* dst = g_xh + (size_t)mz * ELTS;
    const size_t i = (size_t)blockIdx.x * 256 + threadIdx.x;
    const float4 a = reinterpret_cast<const float4*>(src)[i * 2];
    const float4 b = reinterpret_cast<const float4*>(src)[i * 2 + 1];
    __half2 h[4];
    h[0].x = __float2half_rn(a.x); h[0].y = __float2half_rn(a.y);
    h[1].x = __float2half_rn(a.z); h[1].y = __float2half_rn(a.w);
    h[2].x = __float2half_rn(b.x); h[2].y = __float2half_rn(b.y);
    h[3].x = __float2half_rn(b.z); h[3].y = __float2half_rn(b.w);
    reinterpret_cast<float4*>(dst)[i] = *reinterpret_cast<const float4*>(h);
}

// ---------------- weight transpose + fp16 ----------------
__global__ __launch_bounds__(256)
void wt_kernel(const float* __restrict__ w0, const float* __restrict__ w1,
               const float* __restrict__ w2) {
    __shared__ float t[32][33];
    const int mz = blockIdx.z;
    const float* src = (mz == 0) ? w0 : (mz == 1) ? w1 : w2;
    __half* dst = g_Wt + (size_t)mz * DM * DM;
    const int c0 = blockIdx.x * 32, r0 = blockIdx.y * 32;
#pragma unroll
    for (int i = 0; i < 4; ++i) {
        const int r = r0 + threadIdx.y + i * 8;
        t[threadIdx.y + i * 8][threadIdx.x] = src[(size_t)r * DM + c0 + threadIdx.x];
    }
    __syncthreads();
#pragma unroll
    for (int i = 0; i < 4; ++i) {
        const int c = c0 + threadIdx.y + i * 8;
        const int r = r0 + threadIdx.x;
        dst[(size_t)c * DM + r] = __float2half_rn(t[threadIdx.x][threadIdx.y + i * 8]);
    }
}

// ---------------- launch (fork/join: projQ concurrent with projKV+bm) --------
extern "C" void kernel_launch(void* const* d_in, const int* in_sizes, int n_in,
                              void* d_out, int out_size) {
    const float* x_q = (const float*)d_in[0];
    const float* x_k = (const float*)d_in[1];
    const float* x_v = (const float*)d_in[2];
    const float* W_q = (const float*)d_in[3];
    const float* b_q = (const float*)d_in[4];
    const float* W_k = (const float*)d_in[5];
    const float* b_k = (const float*)d_in[6];
    const float* W_v = (const float*)d_in[7];
    const float* b_v = (const float*)d_in[8];
    float* Z = (float*)d_out;

    cudaFuncSetAttribute(proj_all_kernel<0>, cudaFuncAttributeMaxDynamicSharedMemorySize, SMEM_BYTES);
    cudaFuncSetAttribute(proj_all_kernel<1>, cudaFuncAttributeMaxDynamicSharedMemorySize, SMEM_BYTES);
    cudaFuncSetAttribute(bm_split_kernel, cudaFuncAttributeMaxDynamicSharedMemorySize, SMEM_BYTES);
    cudaFuncSetAttribute(z_gemm_kernel, cudaFuncAttributeMaxDynamicSharedMemorySize, SMEM_BYTES);

    // side stream + fork/join events (created fresh each call; NOT destroyed
    // here — destroying a stream with capture-pending work would invalidate
    // graph capture; kernel_launch is only invoked a handful of times).
    cudaStream_t s2;
    cudaStreamCreate(&s2);
    cudaEvent_t evFork, evQ;
    cudaEventCreateWithFlags(&evFork, cudaEventDisableTiming);
    cudaEventCreateWithFlags(&evQ, cudaEventDisableTiming);

    // main stream: conversions
    wt_kernel<<<dim3(16, 16, 3), dim3(32, 8)>>>(W_q, W_k, W_v);
    xconv_kernel<<<dim3((int)(ELTS / 8 / 256), 3), 256>>>(x_q, x_k, x_v);

    // fork: projQ on s2, concurrent with projKV -> bm_split on main stream
    cudaEventRecord(evFork, 0);
    cudaStreamWaitEvent(s2, evFork, 0);

    proj_all_kernel<1><<<dim3(4, 256, 2), 256, SMEM_BYTES>>>(b_q, b_k, b_v);   // KV (main)
    proj_all_kernel<0><<<dim3(4, 256, 1), 256, SMEM_BYTES, s2>>>(b_q, b_k, b_v); // Q (side)
    cudaEventRecord(evQ, s2);

    bm_split_kernel<<<dim3(4, 16, 8), 256, SMEM_BYTES>>>();                    // main

    // join: main stream needs projQ's outputs (pq, eQ)
    cudaStreamWaitEvent(0, evQ, 0);

    combine_sums_kernel<<<8, 512>>>();
    bm_combine_kernel<<<2048, 256>>>();

    z_gemm_kernel<<<dim3(4, 32, 8), 256, SMEM_BYTES>>>(Z);
}

// round 15
// speedup vs baseline: 1.9602x; 1.0217x over previous
#include <cuda_runtime.h>
#include <cuda_fp16.h>
#include <stdint.h>

// ============================================================================
// LightAttention via mma.sync m16n8k16 FP16 (f32 accum), K-chunk 64.
// 128x128 CTA tiles, 8 warps (2Mx4N, warp 64x32), 2 CTAs/SM, 2-stage cp.async.
// Two-stream graph:
//   main: wt -> xconv(K,V) -> projKV -> bm_split -> [wait evS] -> bm_combine -> z
//   side: [wait evW] xconv(Q) -> projQ -> [wait evKV] combine_sums -> evS
//   xconv : x fp32 -> fp16 (RNE);  wt: W [in,out] -> WT [out,in] fp16
//   projKV: eKT[d,n]=exp((xk@Wk+b)^T*s) (+row sums); VT[e,n]=(xv@Wv+b)^T
//   projQ : eQ[n,d]=exp((xq@Wq+b)*s) (+col sums)
//   bm_split (split-K x4, fp32 partials); bm_combine: BmT=(sum)/(ks*qs)*2^15
//   z_gemm: Z = (eQ @ BmT^T) * 2^-15.
// Softmax max dropped (exp args in [-0.75,0.75]; cancels algebraically).
// ============================================================================

#define B_SZ   8
#define N_SEQ  4096
#define DM     512
#define M_ALL  (B_SZ * N_SEQ)
#define ELTS   ((size_t)M_ALL * DM)

static __device__ __constant__ float kINVS = 0.21022410381342863f; // 512^-0.25
#define ZSCALE 0.000030517578125f   // 2^-15
#define BSCALE 32768.0f             // 2^15

// ---------------- scratch ----------------
__device__ __align__(16) __half g_Wt[3 * DM * DM];
__device__ __align__(16) __half g_xh[3 * ELTS];
__device__ __align__(16) __half g_eQ[ELTS];
__device__ __align__(16) __half g_eKT[ELTS];
__device__ __align__(16) __half g_VT[ELTS];
__device__ __align__(16) __half g_BmT[B_SZ * DM * DM];
__device__ __align__(16) float g_BmP[4 * B_SZ * DM * DM];
__device__ float g_pq[256 * DM];
__device__ float g_pk[256 * DM];
__device__ float g_sum[2 * B_SZ * DM];

// ---------------- helpers ----------------
__device__ __forceinline__ uint32_t smem_u32(const void* p) {
    uint32_t r;
    asm("{ .reg .u64 t; cvta.to.shared.u64 t, %1; cvt.u32.u64 %0, t; }" : "=r"(r) : "l"(p));
    return r;
}
__device__ __forceinline__ void ldmx4(uint32_t r[4], uint32_t addr) {
    asm volatile("ldmatrix.sync.aligned.m8n8.x4.shared.b16 {%0,%1,%2,%3}, [%4];"
                 : "=r"(r[0]), "=r"(r[1]), "=r"(r[2]), "=r"(r[3]) : "r"(addr));
}
__device__ __forceinline__ void mma16816(float c[4], const uint32_t a[4], const uint32_t b[2]) {
    asm volatile("mma.sync.aligned.m16n8k16.row.col.f32.f16.f16.f32 "
                 "{%0,%1,%2,%3}, {%4,%5,%6,%7}, {%8,%9}, {%0,%1,%2,%3};"
                 : "+f"(c[0]), "+f"(c[1]), "+f"(c[2]), "+f"(c[3])
                 : "r"(a[0]), "r"(a[1]), "r"(a[2]), "r"(a[3]), "r"(b[0]), "r"(b[1]));
}

#define PITCH    144            // 64 fp16 (128B) + 16B pad; conflict-free
#define MATB     18432          // 128 * 144
#define STAGE_B  36864          // 2 matrices
#define SMEM_BYTES 73728        // 2 stages
#define SPB2     272            // epilogue staging pitch: 128 fp16 + 16B pad
#define SW_OFF   36864

// k64 chunk: A[128,64] @ B[128,64]^T fp16, warps 2Mx4N, warp tile 64x32.
__device__ __forceinline__ void gemm_f16(uint32_t aBase, uint32_t bBase,
                                         int wm, int wn, int lane, float acc[4][4][4]) {
    const int arow = wm * 64 + (lane & 15);
    const uint32_t acolb = (uint32_t)((lane >> 4) * 16);
    const int grp = lane >> 3;
    const int brow = wn * 32 + ((grp >> 1) << 3) + (lane & 7);
    const uint32_t bcolb = (uint32_t)((grp & 1) * 16);
#pragma unroll
    for (int ks = 0; ks < 4; ++ks) {
        const uint32_t kkb = (uint32_t)(ks * 32);
        uint32_t a[4][4], b[4][2];
#pragma unroll
        for (int mt = 0; mt < 4; ++mt)
            ldmx4(a[mt], aBase + (uint32_t)(arow + mt * 16) * PITCH + acolb + kkb);
#pragma unroll
        for (int half = 0; half < 2; ++half) {
            uint32_t r[4];
            ldmx4(r, bBase + (uint32_t)(brow + half * 16) * PITCH + bcolb + kkb);
            b[half * 2][0] = r[0]; b[half * 2][1] = r[1];
            b[half * 2 + 1][0] = r[2]; b[half * 2 + 1][1] = r[3];
        }
#pragma unroll
        for (int mt = 0; mt < 4; ++mt)
#pragma unroll
            for (int nt = 0; nt < 4; ++nt)
                mma16816(acc[mt][nt], a[mt], b[nt]);
    }
}

// ---------------- async stage loader (2 fp16 matrices, 128 rows x 128B) ------
__device__ __forceinline__ void load2h(uint32_t smbase, int s,
                                       const __half* aP, int as,
                                       const __half* bP, int bs, int kc, int tid) {
    const uint32_t base = smbase + s * STAGE_B;
#pragma unroll
    for (int i = 0; i < 4; ++i) {
        const int idx = tid + i * 256, row = idx >> 3, c16 = idx & 7;
        const uint32_t d = base + row * PITCH + c16 * 16;
        const __half* g = aP + (size_t)row * as + kc + c16 * 8;
        asm volatile("cp.async.cg.shared.global [%0], [%1], 16;" :: "r"(d), "l"(g));
    }
#pragma unroll
    for (int i = 0; i < 4; ++i) {
        const int idx = tid + i * 256, row = idx >> 3, c16 = idx & 7;
        const uint32_t d = base + MATB + row * PITCH + c16 * 16;
        const __half* g = bP + (size_t)row * bs + kc + c16 * 8;
        asm volatile("cp.async.cg.shared.global [%0], [%1], 16;" :: "r"(d), "l"(g));
    }
    asm volatile("cp.async.commit_group;");
}

// 2-stage mainloop over NCH chunks of K=64 starting at k0.
template<int NCH>
__device__ __forceinline__ void mainloop2(uint32_t smbase,
                                          const __half* aP, int as,
                                          const __half* bP, int bs, int k0,
                                          int tid, int wm, int wn, int lane,
                                          float acc[4][4][4]) {
    load2h(smbase, 0, aP, as, bP, bs, k0, tid);
#pragma unroll 1
    for (int c = 0; c < NCH; ++c) {
        const int s = c & 1;
        asm volatile("cp.async.wait_group 0;" ::: "memory");
        __syncthreads();
        if (c + 1 < NCH) load2h(smbase, 1 - s, aP, as, bP, bs, k0 + (c + 1) * 64, tid);
        gemm_f16(smbase + s * STAGE_B, smbase + s * STAGE_B + MATB, wm, wn, lane, acc);
    }
}

// ---------------- unified projection, mz = blockIdx.z + MZB ----------------
template<int MZB>
__global__ __launch_bounds__(256, 2)
void proj_all_kernel(const float* __restrict__ bq, const float* __restrict__ bk,
                     const float* __restrict__ bvv) {
    extern __shared__ char smx[];
    const uint32_t smbase = smem_u32(smx);
    const int tid = threadIdx.x, wid = tid >> 5, lane = tid & 31;
    const int wm = wid & 1, wn = wid >> 1;
    const int bx = blockIdx.x, byr = blockIdx.y, mz = blockIdx.z + MZB;
    const bool isQ = (mz == 0);

    const float* bias = (mz == 0) ? bq : (mz == 1) ? bk : bvv;
    const __half* Xh = g_xh + (size_t)mz * ELTS;
    const __half* Wp = g_Wt + (size_t)mz * DM * DM;

    int b = 0, ntile = 0, dtile = 0;
    size_t xRow0, wRow0;
    if (isQ) { xRow0 = (size_t)byr * 128; wRow0 = (size_t)bx * 128; }
    else {
        b = byr >> 5; ntile = byr & 31; dtile = bx;
        xRow0 = (size_t)b * 4096 + (size_t)ntile * 128;
        wRow0 = (size_t)dtile * 128;
    }
    const __half* xP = Xh + xRow0 * 512;
    const __half* wP = Wp + wRow0 * 512;

    float acc[4][4][4];
#pragma unroll
    for (int a = 0; a < 4; ++a)
#pragma unroll
        for (int b2 = 0; b2 < 4; ++b2)
#pragma unroll
            for (int c = 0; c < 4; ++c) acc[a][b2][c] = 0.f;

    if (isQ) mainloop2<8>(smbase, xP, 512, wP, 512, 0, tid, wm, wn, lane, acc);
    else     mainloop2<8>(smbase, wP, 512, xP, 512, 0, tid, wm, wn, lane, acc);
    __syncthreads();

    // ---------------- fused epilogue ----------------
    const int r0 = wm * 64 + (lane >> 2);
    const int c0 = wn * 32 + (lane & 3) * 2;

    float bcol[4][2], brow[4][2];
    if (isQ) {
#pragma unroll
        for (int nt = 0; nt < 4; ++nt) {
            const int cc = bx * 128 + c0 + nt * 8;
            bcol[nt][0] = bias[cc]; bcol[nt][1] = bias[cc + 1];
        }
    } else {
#pragma unroll
        for (int mt = 0; mt < 4; ++mt)
#pragma unroll
            for (int p = 0; p < 2; ++p)
                brow[mt][p] = bias[dtile * 128 + r0 + mt * 16 + p * 8];
    }

    float ps[4][2];
#pragma unroll
    for (int a = 0; a < 4; ++a) { ps[a][0] = 0.f; ps[a][1] = 0.f; }

    char* st = smx;
#pragma unroll
    for (int mt = 0; mt < 4; ++mt)
#pragma unroll
        for (int nt = 0; nt < 4; ++nt)
#pragma unroll
            for (int p = 0; p < 2; ++p) {
                float v0 = acc[mt][nt][p * 2], v1 = acc[mt][nt][p * 2 + 1];
                if (isQ) { v0 += bcol[nt][0]; v1 += bcol[nt][1]; }
                else     { v0 += brow[mt][p]; v1 += brow[mt][p]; }
                if (mz != 2) {
                    v0 = __expf(v0 * kINVS);
                    v1 = __expf(v1 * kINVS);
                }
                const __half h0 = __float2half_rn(v0);
                const __half h1 = __float2half_rn(v1);
                const float q0 = __half2float(h0), q1 = __half2float(h1);
                if (mz == 0) { ps[nt][0] += q0; ps[nt][1] += q1; }
                if (mz == 1) { ps[mt][p] += q0 + q1; }
                const int row = r0 + mt * 16 + p * 8;
                const int col = c0 + nt * 8;
                __half2 o; o.x = h0; o.y = h1;
                *reinterpret_cast<__half2*>(st + row * SPB2 + col * 2) = o;
            }

    float* sW = reinterpret_cast<float*>(smx + SW_OFF);
    if (mz == 0) {
#pragma unroll
        for (int nt = 0; nt < 4; ++nt)
#pragma unroll
            for (int j = 0; j < 2; ++j) {
                ps[nt][j] += __shfl_xor_sync(0xffffffffu, ps[nt][j], 4);
                ps[nt][j] += __shfl_xor_sync(0xffffffffu, ps[nt][j], 8);
                ps[nt][j] += __shfl_xor_sync(0xffffffffu, ps[nt][j], 16);
            }
        if ((lane >> 2) == 0) {
#pragma unroll
            for (int nt = 0; nt < 4; ++nt)
#pragma unroll
                for (int j = 0; j < 2; ++j)
                    sW[wm * 128 + wn * 32 + nt * 8 + (lane & 3) * 2 + j] = ps[nt][j];
        }
    } else if (mz == 1) {
#pragma unroll
        for (int mt = 0; mt < 4; ++mt)
#pragma unroll
            for (int p = 0; p < 2; ++p) {
                ps[mt][p] += __shfl_xor_sync(0xffffffffu, ps[mt][p], 1);
                ps[mt][p] += __shfl_xor_sync(0xffffffffu, ps[mt][p], 2);
            }
        if ((lane & 3) == 0) {
#pragma unroll
            for (int mt = 0; mt < 4; ++mt)
#pragma unroll
                for (int p = 0; p < 2; ++p)
                    sW[wn * 128 + wm * 64 + mt * 16 + p * 8 + (lane >> 2)] = ps[mt][p];
        }
    }
    __syncthreads();

    __half* outP;
    size_t base, stride;
    if (isQ) {
        outP = g_eQ; stride = 512;
        base = (size_t)byr * 128 * 512 + bx * 128;
    } else {
        outP = (mz == 1) ? g_eKT : g_VT; stride = 4096;
        base = ((size_t)b * 512 + dtile * 128) * 4096 + (size_t)ntile * 128;
    }
#pragma unroll
    for (int it = 0; it < 8; ++it) {
        const int idx = tid + it * 256, row = idx >> 4, seg = idx & 15;
        const float4 v = *reinterpret_cast<const float4*>(st + row * SPB2 + seg * 16);
        *reinterpret_cast<float4*>(
            reinterpret_cast<char*>(outP) + (base + (size_t)row * stride + seg * 8) * 2) = v;
    }
    if (mz == 0 && tid < 128)
        g_pq[(size_t)byr * 512 + bx * 128 + tid] = sW[tid] + sW[128 + tid];
    if (mz == 1 && tid < 128)
        g_pk[((size_t)b * 32 + ntile) * 512 + dtile * 128 + tid] =
            sW[tid] + sW[128 + tid] + sW[256 + tid] + sW[384 + tid];
}

// ---------------- combine sums ----------------
__global__ __launch_bounds__(512)
void combine_sums_kernel() {
    const int i = blockIdx.x * 512 + threadIdx.x;
    const int b = i >> 9, d = i & 511;
    float q = 0.f, k = 0.f;
#pragma unroll
    for (int j = 0; j < 32; ++j) {
        q += g_pq[(b * 32 + j) * 512 + d];
        k += g_pk[(b * 32 + j) * 512 + d];
    }
    g_sum[i] = q;
    g_sum[4096 + i] = k;
}

// ---------------- Bm split-K x4: grid (4, 16, 8) ----------------
__global__ __launch_bounds__(256, 2)
void bm_split_kernel() {
    extern __shared__ char smx[];
    const uint32_t smbase = smem_u32(smx);
    const int tid = threadIdx.x, wid = tid >> 5, lane = tid & 31;
    const int wm = wid & 1, wn = wid >> 1;
    const int bx = blockIdx.x, bz = blockIdx.z;
    const int split = blockIdx.y >> 2, ey = blockIdx.y & 3;
    const int k0 = split * 1024;

    const __half* aP = g_VT + ((size_t)bz * 512 + ey * 128) * 4096;
    const __half* bP = g_eKT + ((size_t)bz * 512 + bx * 128) * 4096;

    float acc[4][4][4];
#pragma unroll
    for (int a = 0; a < 4; ++a)
#pragma unroll
        for (int b2 = 0; b2 < 4; ++b2)
#pragma unroll
            for (int c = 0; c < 4; ++c) acc[a][b2][c] = 0.f;

    mainloop2<16>(smbase, aP, 4096, bP, 4096, k0, tid, wm, wn, lane, acc);

    const int r0 = wm * 64 + (lane >> 2);
    const int c0 = wn * 32 + (lane & 3) * 2;
    float* outP = g_BmP + ((size_t)split * 8 + bz) * DM * DM;
#pragma unroll
    for (int mt = 0; mt < 4; ++mt)
#pragma unroll
        for (int nt = 0; nt < 4; ++nt)
#pragma unroll
            for (int p = 0; p < 2; ++p) {
                const int e = ey * 128 + r0 + mt * 16 + p * 8;
                const int d = bx * 128 + c0 + nt * 8;
                float2 o;
                o.x = acc[mt][nt][p * 2];
                o.y = acc[mt][nt][p * 2 + 1];
                *reinterpret_cast<float2*>(outP + (size_t)e * DM + d) = o;
            }
}

// ---------------- Bm combine: sum, scale by 2^15/(ks*qs), fp16 ----------------
__global__ __launch_bounds__(256)
void bm_combine_kernel() {
    const size_t idx = (size_t)blockIdx.x * 256 + threadIdx.x;
    const size_t e4 = idx * 4;
    const int bz = (int)(e4 >> 18);
    const int d0 = (int)(e4 & 511);
    float4 s = reinterpret_cast<const float4*>(g_BmP)[idx];
#pragma unroll
    for (int sp = 1; sp < 4; ++sp) {
        const float4 t = reinterpret_cast<const float4*>(g_BmP + (size_t)sp * 8 * DM * DM)[idx];
        s.x += t.x; s.y += t.y; s.z += t.z; s.w += t.w;
    }
    const float* sq = g_sum + bz * 512 + d0;
    const float* sk = g_sum + 4096 + bz * 512 + d0;
    __half2 lo, hi;
    lo.x = __float2half_rn(s.x * BSCALE / (sk[0] * sq[0]));
    lo.y = __float2half_rn(s.y * BSCALE / (sk[1] * sq[1]));
    hi.x = __float2half_rn(s.z * BSCALE / (sk[2] * sq[2]));
    hi.y = __float2half_rn(s.w * BSCALE / (sk[3] * sq[3]));
    reinterpret_cast<__half2*>(g_BmT)[idx * 2] = lo;
    reinterpret_cast<__half2*>(g_BmT)[idx * 2 + 1] = hi;
}

// ---------------- Z GEMM: grid (4, 32, 8), out = acc * 2^-15 ----------------
__global__ __launch_bounds__(256, 2)
void z_gemm_kernel(float* __restrict__ Z) {
    extern __shared__ char smx[];
    const uint32_t smbase = smem_u32(smx);
    const int tid = threadIdx.x, wid = tid >> 5, lane = tid & 31;
    const int wm = wid & 1, wn = wid >> 1;
    const int bx = blockIdx.x, by = blockIdx.y, bz = blockIdx.z;

    const __half* aP = g_eQ + ((size_t)bz * 4096 + by * 128) * 512;
    const __half* bP = g_BmT + ((size_t)bz * 512 + bx * 128) * 512;

    float acc[4][4][4];
#pragma unroll
    for (int a = 0; a < 4; ++a)
#pragma unroll
        for (int b2 = 0; b2 < 4; ++b2)
#pragma unroll
            for (int c = 0; c < 4; ++c) acc[a][b2][c] = 0.f;

    mainloop2<8>(smbase, aP, 512, bP, 512, 0, tid, wm, wn, lane, acc);

    const int r0 = wm * 64 + (lane >> 2);
    const int c0 = wn * 32 + (lane & 3) * 2;
#pragma unroll
    for (int mt = 0; mt < 4; ++mt)
#pragma unroll
        for (int nt = 0; nt < 4; ++nt)
#pragma unroll
            for (int p = 0; p < 2; ++p) {
                const int cc = bx * 128 + c0 + nt * 8;
                const size_t row = (size_t)bz * 4096 + by * 128 + r0 + mt * 16 + p * 8;
                float2 o;
                o.x = acc[mt][nt][p * 2] * ZSCALE;
                o.y = acc[mt][nt][p * 2 + 1] * ZSCALE;
                *reinterpret_cast<float2*>(Z + row * 512 + cc) = o;
            }
}

// ---------------- x fp32 -> fp16, mz = blockIdx.y + MZB ----------------
template<int MZB>
__global__ __launch_bounds__(256)
void xconv_kernel(const float* __restrict__ x0, const float* __restrict__ x1,
                  const float* __restrict__ x2) {
    const int mz = blockIdx.y + MZB;
    const float* src = (mz == 0) ? x0 : (mz == 1) ? x1 : x2;
    __half* dst = g_xh + (size_t)mz * ELTS;
    const size_t i = (size_t)blockIdx.x * 256 + threadIdx.x;
    const float4 a = reinterpret_cast<const float4*>(src)[i * 2];
    const float4 b = reinterpret_cast<const float4*>(src)[i * 2 + 1];
    __half2 h[4];
    h[0].x = __float2half_rn(a.x); h[0].y = __float2half_rn(a.y);
    h[1].x = __float2half_rn(a.z); h[1].y = __float2half_rn(a.w);
    h[2].x = __float2half_rn(b.x); h[2].y = __float2half_rn(b.y);
    h[3].x = __float2half_rn(b.z); h[3].y = __float2half_rn(b.w);
    reinterpret_cast<float4*>(dst)[i] = *reinterpret_cast<const float4*>(h);
}

// ---------------- weight transpose + fp16 ----------------
__global__ __launch_bounds__(256)
void wt_kernel(const float* __restrict__ w0, const float* __restrict__ w1,
               const float* __restrict__ w2) {
    __shared__ float t[32][33];
    const int mz = blockIdx.z;
    const float* src = (mz == 0) ? w0 : (mz == 1) ? w1 : w2;
    __half* dst = g_Wt + (size_t)mz * DM * DM;
    const int c0 = blockIdx.x * 32, r0 = blockIdx.y * 32;
#pragma unroll
    for (int i = 0; i < 4; ++i) {
        const int r = r0 + threadIdx.y + i * 8;
        t[threadIdx.y + i * 8][threadIdx.x] = src[(size_t)r * DM + c0 + threadIdx.x];
    }
    __syncthreads();
#pragma unroll
    for (int i = 0; i < 4; ++i) {
        const int c = c0 + threadIdx.y + i * 8;
        const int r = r0 + threadIdx.x;
        dst[(size_t)c * DM + r] = __float2half_rn(t[threadIdx.x][threadIdx.y + i * 8]);
    }
}

// ---------------- launch: two-stream overlapped graph ----------------
extern "C" void kernel_launch(void* const* d_in, const int* in_sizes, int n_in,
                              void* d_out, int out_size) {
    const float* x_q = (const float*)d_in[0];
    const float* x_k = (const float*)d_in[1];
    const float* x_v = (const float*)d_in[2];
    const float* W_q = (const float*)d_in[3];
    const float* b_q = (const float*)d_in[4];
    const float* W_k = (const float*)d_in[5];
    const float* b_k = (const float*)d_in[6];
    const float* W_v = (const float*)d_in[7];
    const float* b_v = (const float*)d_in[8];
    float* Z = (float*)d_out;

    cudaFuncSetAttribute(proj_all_kernel<0>, cudaFuncAttributeMaxDynamicSharedMemorySize, SMEM_BYTES);
    cudaFuncSetAttribute(proj_all_kernel<1>, cudaFuncAttributeMaxDynamicSharedMemorySize, SMEM_BYTES);
    cudaFuncSetAttribute(bm_split_kernel, cudaFuncAttributeMaxDynamicSharedMemorySize, SMEM_BYTES);
    cudaFuncSetAttribute(z_gemm_kernel, cudaFuncAttributeMaxDynamicSharedMemorySize, SMEM_BYTES);

    // side stream + events (created per call, not destroyed: destroying with
    // capture-pending work would invalidate graph capture).
    cudaStream_t s2;
    cudaStreamCreate(&s2);
    cudaEvent_t evW, evKV, evS;
    cudaEventCreateWithFlags(&evW, cudaEventDisableTiming);
    cudaEventCreateWithFlags(&evKV, cudaEventDisableTiming);
    cudaEventCreateWithFlags(&evS, cudaEventDisableTiming);

    const int xblk = (int)(ELTS / 8 / 256);

    // main: weights, then fork point for the Q chain
    wt_kernel<<<dim3(16, 16, 3), dim3(32, 8)>>>(W_q, W_k, W_v);
    cudaEventRecord(evW, 0);

    // main: K/V conversion -> projKV -> bm_split
    xconv_kernel<1><<<dim3(xblk, 2), 256>>>(x_q, x_k, x_v);
    proj_all_kernel<1><<<dim3(4, 256, 2), 256, SMEM_BYTES>>>(b_q, b_k, b_v);
    cudaEventRecord(evKV, 0);
    bm_split_kernel<<<dim3(4, 16, 8), 256, SMEM_BYTES>>>();

    // side: Q conversion -> projQ -> (after projKV) combine_sums
    cudaStreamWaitEvent(s2, evW, 0);
    xconv_kernel<0><<<dim3(xblk, 1), 256, 0, s2>>>(x_q, x_k, x_v);
    proj_all_kernel<0><<<dim3(4, 256, 1), 256, SMEM_BYTES, s2>>>(b_q, b_k, b_v);
    cudaStreamWaitEvent(s2, evKV, 0);
    combine_sums_kernel<<<8, 512, 0, s2>>>();
    cudaEventRecord(evS, s2);

    // join: bm_combine needs sums (evS) + bm partials (main order)
    cudaStreamWaitEvent(0, evS, 0);
    bm_combine_kernel<<<2048, 256>>>();
    z_gemm_kernel<<<dim3(4, 32, 8), 256, SMEM_BYTES>>>(Z);
}

// round 16
// speedup vs baseline: 2.0445x; 1.0430x over previous
#include <cuda_runtime.h>
#include <cuda_fp16.h>
#include <stdint.h>

// ============================================================================
// LightAttention via mma.sync m16n8k16 FP16 (f32 accum), K-chunk 64.
// 128x128 CTA tiles, 8 warps (2Mx4N, warp 64x32), 2 CTAs/SM, 2-stage pipeline.
// x fp32->fp16 conversion FUSED into proj mainloop (LDG->cvt->STS for the x
// operand; W via cp.async) -- no standalone conversion pass.
// Two-stream graph:
//   main: wt -> projKV -> bm_split -> [wait evS] -> bm_combine -> z
//   side: [wait evW] projQ -> [wait evKV] combine_sums -> evS
//   projKV: eKT[d,n]=exp((xk@Wk+b)^T*s) (+row sums); VT[e,n]=(xv@Wv+b)^T
//   projQ : eQ[n,d]=exp((xq@Wq+b)*s) (+col sums)
//   bm_split (split-K x2, ONE wave, fp32 partials);
//   bm_combine: BmT=(sum)/(ks*qs)*2^15 -> fp16 (subnormal guard)
//   z_gemm: Z = (eQ @ BmT^T) * 2^-15.
// Softmax max dropped (exp args in [-0.75,0.75]; cancels algebraically).
// ============================================================================

#define B_SZ   8
#define N_SEQ  4096
#define DM     512
#define M_ALL  (B_SZ * N_SEQ)
#define ELTS   ((size_t)M_ALL * DM)

static __device__ __constant__ float kINVS = 0.21022410381342863f; // 512^-0.25
#define ZSCALE 0.000030517578125f   // 2^-15
#define BSCALE 32768.0f             // 2^15

// ---------------- scratch ----------------
__device__ __align__(16) __half g_Wt[3 * DM * DM];
__device__ __align__(16) __half g_eQ[ELTS];
__device__ __align__(16) __half g_eKT[ELTS];
__device__ __align__(16) __half g_VT[ELTS];
__device__ __align__(16) __half g_BmT[B_SZ * DM * DM];
__device__ __align__(16) float g_BmP[2 * B_SZ * DM * DM];
__device__ float g_pq[256 * DM];
__device__ float g_pk[256 * DM];
__device__ float g_sum[2 * B_SZ * DM];

// ---------------- helpers ----------------
__device__ __forceinline__ uint32_t smem_u32(const void* p) {
    uint32_t r;
    asm("{ .reg .u64 t; cvta.to.shared.u64 t, %1; cvt.u32.u64 %0, t; }" : "=r"(r) : "l"(p));
    return r;
}
__device__ __forceinline__ void ldmx4(uint32_t r[4], uint32_t addr) {
    asm volatile("ldmatrix.sync.aligned.m8n8.x4.shared.b16 {%0,%1,%2,%3}, [%4];"
                 : "=r"(r[0]), "=r"(r[1]), "=r"(r[2]), "=r"(r[3]) : "r"(addr));
}
__device__ __forceinline__ void mma16816(float c[4], const uint32_t a[4], const uint32_t b[2]) {
    asm volatile("mma.sync.aligned.m16n8k16.row.col.f32.f16.f16.f32 "
                 "{%0,%1,%2,%3}, {%4,%5,%6,%7}, {%8,%9}, {%0,%1,%2,%3};"
                 : "+f"(c[0]), "+f"(c[1]), "+f"(c[2]), "+f"(c[3])
                 : "r"(a[0]), "r"(a[1]), "r"(a[2]), "r"(a[3]), "r"(b[0]), "r"(b[1]));
}

#define PITCH    144            // 64 fp16 (128B) + 16B pad; conflict-free
#define MATB     18432          // 128 * 144
#define STAGE_B  36864          // 2 matrices
#define SMEM_BYTES 73728        // 2 stages
#define SPB2     272            // epilogue staging pitch: 128 fp16 + 16B pad
#define SW_OFF   36864

// k64 chunk: A[128,64] @ B[128,64]^T fp16, warps 2Mx4N, warp tile 64x32.
__device__ __forceinline__ void gemm_f16(uint32_t aBase, uint32_t bBase,
                                         int wm, int wn, int lane, float acc[4][4][4]) {
    const int arow = wm * 64 + (lane & 15);
    const uint32_t acolb = (uint32_t)((lane >> 4) * 16);
    const int grp = lane >> 3;
    const int brow = wn * 32 + ((grp >> 1) << 3) + (lane & 7);
    const uint32_t bcolb = (uint32_t)((grp & 1) * 16);
#pragma unroll
    for (int ks = 0; ks < 4; ++ks) {
        const uint32_t kkb = (uint32_t)(ks * 32);
        uint32_t a[4][4], b[4][2];
#pragma unroll
        for (int mt = 0; mt < 4; ++mt)
            ldmx4(a[mt], aBase + (uint32_t)(arow + mt * 16) * PITCH + acolb + kkb);
#pragma unroll
        for (int half = 0; half < 2; ++half) {
            uint32_t r[4];
            ldmx4(r, bBase + (uint32_t)(brow + half * 16) * PITCH + bcolb + kkb);
            b[half * 2][0] = r[0]; b[half * 2][1] = r[1];
            b[half * 2 + 1][0] = r[2]; b[half * 2 + 1][1] = r[3];
        }
#pragma unroll
        for (int mt = 0; mt < 4; ++mt)
#pragma unroll
            for (int nt = 0; nt < 4; ++nt)
                mma16816(acc[mt][nt], a[mt], b[nt]);
    }
}

// ---------------- async stage loader (2 fp16 matrices, 128 rows x 128B) ------
__device__ __forceinline__ void load2h(uint32_t smbase, int s,
                                       const __half* aP, int as,
                                       const __half* bP, int bs, int kc, int tid) {
    const uint32_t base = smbase + s * STAGE_B;
#pragma unroll
    for (int i = 0; i < 4; ++i) {
        const int idx = tid + i * 256, row = idx >> 3, c16 = idx & 7;
        const uint32_t d = base + row * PITCH + c16 * 16;
        const __half* g = aP + (size_t)row * as + kc + c16 * 8;
        asm volatile("cp.async.cg.shared.global [%0], [%1], 16;" :: "r"(d), "l"(g));
    }
#pragma unroll
    for (int i = 0; i < 4; ++i) {
        const int idx = tid + i * 256, row = idx >> 3, c16 = idx & 7;
        const uint32_t d = base + MATB + row * PITCH + c16 * 16;
        const __half* g = bP + (size_t)row * bs + kc + c16 * 8;
        asm volatile("cp.async.cg.shared.global [%0], [%1], 16;" :: "r"(d), "l"(g));
    }
    asm volatile("cp.async.commit_group;");
}

// 2-stage mainloop over NCH chunks of K=64 starting at k0 (pure async).
template<int NCH>
__device__ __forceinline__ void mainloop2(uint32_t smbase,
                                          const __half* aP, int as,
                                          const __half* bP, int bs, int k0,
                                          int tid, int wm, int wn, int lane,
                                          float acc[4][4][4]) {
    load2h(smbase, 0, aP, as, bP, bs, k0, tid);
#pragma unroll 1
    for (int c = 0; c < NCH; ++c) {
        const int s = c & 1;
        asm volatile("cp.async.wait_group 0;" ::: "memory");
        __syncthreads();
        if (c + 1 < NCH) load2h(smbase, 1 - s, aP, as, bP, bs, k0 + (c + 1) * 64, tid);
        gemm_f16(smbase + s * STAGE_B, smbase + s * STAGE_B + MATB, wm, wn, lane, acc);
    }
}

// ---------------- unified projection (fused x conversion) ----------------
// mz = blockIdx.z + MZB.  mz0: A=x(conv) B=W(async), out eQ[n,d]+col sums.
// mz1: A=W(async) B=x(conv), out eKT[d,n]+row sums.  mz2: same, out VT[e,n].
template<int MZB>
__global__ __launch_bounds__(256, 2)
void proj_all_kernel(const float* __restrict__ xq, const float* __restrict__ xk,
                     const float* __restrict__ xv,
                     const float* __restrict__ bq, const float* __restrict__ bk,
                     const float* __restrict__ bvv) {
    extern __shared__ char smx[];
    const uint32_t smbase = smem_u32(smx);
    const int tid = threadIdx.x, wid = tid >> 5, lane = tid & 31;
    const int wm = wid & 1, wn = wid >> 1;
    const int bx = blockIdx.x, byr = blockIdx.y, mz = blockIdx.z + MZB;
    const bool isQ = (mz == 0);

    const float* X = (mz == 0) ? xq : (mz == 1) ? xk : xv;
    const float* bias = (mz == 0) ? bq : (mz == 1) ? bk : bvv;
    const __half* Wp = g_Wt + (size_t)mz * DM * DM;

    int b = 0, ntile = 0, dtile = 0;
    size_t xRow0, wRow0;
    if (isQ) { xRow0 = (size_t)byr * 128; wRow0 = (size_t)bx * 128; }
    else {
        b = byr >> 5; ntile = byr & 31; dtile = bx;
        xRow0 = (size_t)b * 4096 + (size_t)ntile * 128;
        wRow0 = (size_t)dtile * 128;
    }
    const float* xP = X + xRow0 * 512;
    const __half* wP = Wp + wRow0 * 512;
    const uint32_t convOff = isQ ? 0u : (uint32_t)MATB;  // x matrix slot
    const uint32_t asyOff  = isQ ? (uint32_t)MATB : 0u;  // W matrix slot

    // conversion staging: 128 rows x 64 fp32 per chunk, 32 elts/thread
    float4 cr[4][2];
    auto ldgConv = [&](int kc) {
#pragma unroll
        for (int j = 0; j < 4; ++j) {
            const int lin = tid + j * 256, row = lin >> 3, kq = lin & 7;
            const float* g = xP + (size_t)row * 512 + kc + kq * 8;
            cr[j][0] = *reinterpret_cast<const float4*>(g);
            cr[j][1] = *reinterpret_cast<const float4*>(g + 4);
        }
    };
    auto stsConv = [&](int s) {
        char* bp = smx + s * STAGE_B + convOff;
#pragma unroll
        for (int j = 0; j < 4; ++j) {
            const int lin = tid + j * 256, row = lin >> 3, kq = lin & 7;
            __half2 h[4];
            h[0].x = __float2half_rn(cr[j][0].x); h[0].y = __float2half_rn(cr[j][0].y);
            h[1].x = __float2half_rn(cr[j][0].z); h[1].y = __float2half_rn(cr[j][0].w);
            h[2].x = __float2half_rn(cr[j][1].x); h[2].y = __float2half_rn(cr[j][1].y);
            h[3].x = __float2half_rn(cr[j][1].z); h[3].y = __float2half_rn(cr[j][1].w);
            *reinterpret_cast<float4*>(bp + row * PITCH + kq * 16) =
                *reinterpret_cast<const float4*>(h);
        }
    };
    auto asyncLoad = [&](int s, int kc) {
        const uint32_t d0 = smbase + s * STAGE_B + asyOff;
#pragma unroll
        for (int i = 0; i < 4; ++i) {
            const int idx = tid + i * 256, row = idx >> 3, c16 = idx & 7;
            const uint32_t d = d0 + row * PITCH + c16 * 16;
            const __half* g = wP + (size_t)row * 512 + kc + c16 * 8;
            asm volatile("cp.async.cg.shared.global [%0], [%1], 16;" :: "r"(d), "l"(g));
        }
        asm volatile("cp.async.commit_group;");
    };

    float acc[4][4][4];
#pragma unroll
    for (int a = 0; a < 4; ++a)
#pragma unroll
        for (int b2 = 0; b2 < 4; ++b2)
#pragma unroll
            for (int c = 0; c < 4; ++c) acc[a][b2][c] = 0.f;

    // prologue
    ldgConv(0);
    stsConv(0);
    asyncLoad(0, 0);
    ldgConv(64);

#pragma unroll 1
    for (int c = 0; c < 8; ++c) {
        const int s = c & 1;
        asm volatile("cp.async.wait_group 0;" ::: "memory");
        __syncthreads();
        if (c + 1 < 8) { asyncLoad(1 - s, (c + 1) * 64); stsConv(1 - s); }
        if (c + 2 < 8) ldgConv((c + 2) * 64);
        gemm_f16(smbase + s * STAGE_B, smbase + s * STAGE_B + MATB, wm, wn, lane, acc);
    }
    __syncthreads();

    // ---------------- fused epilogue ----------------
    const int r0 = wm * 64 + (lane >> 2);
    const int c0 = wn * 32 + (lane & 3) * 2;

    float bcol[4][2], brow[4][2];
    if (isQ) {
#pragma unroll
        for (int nt = 0; nt < 4; ++nt) {
            const int cc = bx * 128 + c0 + nt * 8;
            bcol[nt][0] = bias[cc]; bcol[nt][1] = bias[cc + 1];
        }
    } else {
#pragma unroll
        for (int mt = 0; mt < 4; ++mt)
#pragma unroll
            for (int p = 0; p < 2; ++p)
                brow[mt][p] = bias[dtile * 128 + r0 + mt * 16 + p * 8];
    }

    float ps[4][2];
#pragma unroll
    for (int a = 0; a < 4; ++a) { ps[a][0] = 0.f; ps[a][1] = 0.f; }

    char* st = smx;
#pragma unroll
    for (int mt = 0; mt < 4; ++mt)
#pragma unroll
        for (int nt = 0; nt < 4; ++nt)
#pragma unroll
            for (int p = 0; p < 2; ++p) {
                float v0 = acc[mt][nt][p * 2], v1 = acc[mt][nt][p * 2 + 1];
                if (isQ) { v0 += bcol[nt][0]; v1 += bcol[nt][1]; }
                else     { v0 += brow[mt][p]; v1 += brow[mt][p]; }
                if (mz != 2) {
                    v0 = __expf(v0 * kINVS);
                    v1 = __expf(v1 * kINVS);
                }
                const __half h0 = __float2half_rn(v0);
                const __half h1 = __float2half_rn(v1);
                const float q0 = __half2float(h0), q1 = __half2float(h1);
                if (mz == 0) { ps[nt][0] += q0; ps[nt][1] += q1; }
                if (mz == 1) { ps[mt][p] += q0 + q1; }
                const int row = r0 + mt * 16 + p * 8;
                const int col = c0 + nt * 8;
                __half2 o; o.x = h0; o.y = h1;
                *reinterpret_cast<__half2*>(st + row * SPB2 + col * 2) = o;
            }

    float* sW = reinterpret_cast<float*>(smx + SW_OFF);
    if (mz == 0) {
#pragma unroll
        for (int nt = 0; nt < 4; ++nt)
#pragma unroll
            for (int j = 0; j < 2; ++j) {
                ps[nt][j] += __shfl_xor_sync(0xffffffffu, ps[nt][j], 4);
                ps[nt][j] += __shfl_xor_sync(0xffffffffu, ps[nt][j], 8);
                ps[nt][j] += __shfl_xor_sync(0xffffffffu, ps[nt][j], 16);
            }
        if ((lane >> 2) == 0) {
#pragma unroll
            for (int nt = 0; nt < 4; ++nt)
#pragma unroll
                for (int j = 0; j < 2; ++j)
                    sW[wm * 128 + wn * 32 + nt * 8 + (lane & 3) * 2 + j] = ps[nt][j];
        }
    } else if (mz == 1) {
#pragma unroll
        for (int mt = 0; mt < 4; ++mt)
#pragma unroll
            for (int p = 0; p < 2; ++p) {
                ps[mt][p] += __shfl_xor_sync(0xffffffffu, ps[mt][p], 1);
                ps[mt][p] += __shfl_xor_sync(0xffffffffu, ps[mt][p], 2);
            }
        if ((lane & 3) == 0) {
#pragma unroll
            for (int mt = 0; mt < 4; ++mt)
#pragma unroll
                for (int p = 0; p < 2; ++p)
                    sW[wn * 128 + wm * 64 + mt * 16 + p * 8 + (lane >> 2)] = ps[mt][p];
        }
    }
    __syncthreads();

    __half* outP;
    size_t base, stride;
    if (isQ) {
        outP = g_eQ; stride = 512;
        base = (size_t)byr * 128 * 512 + bx * 128;
    } else {
        outP = (mz == 1) ? g_eKT : g_VT; stride = 4096;
        base = ((size_t)b * 512 + dtile * 128) * 4096 + (size_t)ntile * 128;
    }
#pragma unroll
    for (int it = 0; it < 8; ++it) {
        const int idx = tid + it * 256, row = idx >> 4, seg = idx & 15;
        const float4 v = *reinterpret_cast<const float4*>(st + row * SPB2 + seg * 16);
        *reinterpret_cast<float4*>(
            reinterpret_cast<char*>(outP) + (base + (size_t)row * stride + seg * 8) * 2) = v;
    }
    if (mz == 0 && tid < 128)
        g_pq[(size_t)byr * 512 + bx * 128 + tid] = sW[tid] + sW[128 + tid];
    if (mz == 1 && tid < 128)
        g_pk[((size_t)b * 32 + ntile) * 512 + dtile * 128 + tid] =
            sW[tid] + sW[128 + tid] + sW[256 + tid] + sW[384 + tid];
}

// ---------------- combine sums ----------------
__global__ __launch_bounds__(512)
void combine_sums_kernel() {
    const int i = blockIdx.x * 512 + threadIdx.x;
    const int b = i >> 9, d = i & 511;
    float q = 0.f, k = 0.f;
#pragma unroll
    for (int j = 0; j < 32; ++j) {
        q += g_pq[(b * 32 + j) * 512 + d];
        k += g_pk[(b * 32 + j) * 512 + d];
    }
    g_sum[i] = q;
    g_sum[4096 + i] = k;
}

// ---------------- Bm split-K x2: grid (4, 8, 8) = 256 CTAs (ONE wave) --------
__global__ __launch_bounds__(256, 2)
void bm_split_kernel() {
    extern __shared__ char smx[];
    const uint32_t smbase = smem_u32(smx);
    const int tid = threadIdx.x, wid = tid >> 5, lane = tid & 31;
    const int wm = wid & 1, wn = wid >> 1;
    const int bx = blockIdx.x, bz = blockIdx.z;
    const int split = blockIdx.y >> 2, ey = blockIdx.y & 3;
    const int k0 = split * 2048;

    const __half* aP = g_VT + ((size_t)bz * 512 + ey * 128) * 4096;
    const __half* bP = g_eKT + ((size_t)bz * 512 + bx * 128) * 4096;

    float acc[4][4][4];
#pragma unroll
    for (int a = 0; a < 4; ++a)
#pragma unroll
        for (int b2 = 0; b2 < 4; ++b2)
#pragma unroll
            for (int c = 0; c < 4; ++c) acc[a][b2][c] = 0.f;

    mainloop2<32>(smbase, aP, 4096, bP, 4096, k0, tid, wm, wn, lane, acc);

    const int r0 = wm * 64 + (lane >> 2);
    const int c0 = wn * 32 + (lane & 3) * 2;
    float* outP = g_BmP + ((size_t)split * 8 + bz) * DM * DM;
#pragma unroll
    for (int mt = 0; mt < 4; ++mt)
#pragma unroll
        for (int nt = 0; nt < 4; ++nt)
#pragma unroll
            for (int p = 0; p < 2; ++p) {
                const int e = ey * 128 + r0 + mt * 16 + p * 8;
                const int d = bx * 128 + c0 + nt * 8;
                float2 o;
                o.x = acc[mt][nt][p * 2];
                o.y = acc[mt][nt][p * 2 + 1];
                *reinterpret_cast<float2*>(outP + (size_t)e * DM + d) = o;
            }
}

// ---------------- Bm combine: sum 2 partials, scale by 2^15/(ks*qs), fp16 ----
__global__ __launch_bounds__(256)
void bm_combine_kernel() {
    const size_t idx = (size_t)blockIdx.x * 256 + threadIdx.x;
    const size_t e4 = idx * 4;
    const int bz = (int)(e4 >> 18);
    const int d0 = (int)(e4 & 511);
    float4 s = reinterpret_cast<const float4*>(g_BmP)[idx];
    const float4 t = reinterpret_cast<const float4*>(g_BmP + (size_t)8 * DM * DM)[idx];
    s.x += t.x; s.y += t.y; s.z += t.z; s.w += t.w;
    const float* sq = g_sum + bz * 512 + d0;
    const float* sk = g_sum + 4096 + bz * 512 + d0;
    __half2 lo, hi;
    lo.x = __float2half_rn(s.x * BSCALE / (sk[0] * sq[0]));
    lo.y = __float2half_rn(s.y * BSCALE / (sk[1] * sq[1]));
    hi.x = __float2half_rn(s.z * BSCALE / (sk[2] * sq[2]));
    hi.y = __float2half_rn(s.w * BSCALE / (sk[3] * sq[3]));
    reinterpret_cast<__half2*>(g_BmT)[idx * 2] = lo;
    reinterpret_cast<__half2*>(g_BmT)[idx * 2 + 1] = hi;
}

// ---------------- Z GEMM: grid (4, 32, 8), out = acc * 2^-15 ----------------
__global__ __launch_bounds__(256, 2)
void z_gemm_kernel(float* __restrict__ Z) {
    extern __shared__ char smx[];
    const uint32_t smbase = smem_u32(smx);
    const int tid = threadIdx.x, wid = tid >> 5, lane = tid & 31;
    const int wm = wid & 1, wn = wid >> 1;
    const int bx = blockIdx.x, by = blockIdx.y, bz = blockIdx.z;

    const __half* aP = g_eQ + ((size_t)bz * 4096 + by * 128) * 512;
    const __half* bP = g_BmT + ((size_t)bz * 512 + bx * 128) * 512;

    float acc[4][4][4];
#pragma unroll
    for (int a = 0; a < 4; ++a)
#pragma unroll
        for (int b2 = 0; b2 < 4; ++b2)
#pragma unroll
            for (int c = 0; c < 4; ++c) acc[a][b2][c] = 0.f;

    mainloop2<8>(smbase, aP, 512, bP, 512, 0, tid, wm, wn, lane, acc);

    const int r0 = wm * 64 + (lane >> 2);
    const int c0 = wn * 32 + (lane & 3) * 2;
#pragma unroll
    for (int mt = 0; mt < 4; ++mt)
#pragma unroll
        for (int nt = 0; nt < 4; ++nt)
#pragma unroll
            for (int p = 0; p < 2; ++p) {
                const int cc = bx * 128 + c0 + nt * 8;
                const size_t row = (size_t)bz * 4096 + by * 128 + r0 + mt * 16 + p * 8;
                float2 o;
                o.x = acc[mt][nt][p * 2] * ZSCALE;
                o.y = acc[mt][nt][p * 2 + 1] * ZSCALE;
                *reinterpret_cast<float2*>(Z + row * 512 + cc) = o;
            }
}

// ---------------- weight transpose + fp16 ----------------
__global__ __launch_bounds__(256)
void wt_kernel(const float* __restrict__ w0, const float* __restrict__ w1,
               const float* __restrict__ w2) {
    __shared__ float t[32][33];
    const int mz = blockIdx.z;
    const float* src = (mz == 0) ? w0 : (mz == 1) ? w1 : w2;
    __half* dst = g_Wt + (size_t)mz * DM * DM;
    const int c0 = blockIdx.x * 32, r0 = blockIdx.y * 32;
#pragma unroll
    for (int i = 0; i < 4; ++i) {
        const int r = r0 + threadIdx.y + i * 8;
        t[threadIdx.y + i * 8][threadIdx.x] = src[(size_t)r * DM + c0 + threadIdx.x];
    }
    __syncthreads();
#pragma unroll
    for (int i = 0; i < 4; ++i) {
        const int c = c0 + threadIdx.y + i * 8;
        const int r = r0 + threadIdx.x;
        dst[(size_t)c * DM + r] = __float2half_rn(t[threadIdx.x][threadIdx.y + i * 8]);
    }
}

// ---------------- launch: two-stream overlapped graph ----------------
extern "C" void kernel_launch(void* const* d_in, const int* in_sizes, int n_in,
                              void* d_out, int out_size) {
    const float* x_q = (const float*)d_in[0];
    const float* x_k = (const float*)d_in[1];
    const float* x_v = (const float*)d_in[2];
    const float* W_q = (const float*)d_in[3];
    const float* b_q = (const float*)d_in[4];
    const float* W_k = (const float*)d_in[5];
    const float* b_k = (const float*)d_in[6];
    const float* W_v = (const float*)d_in[7];
    const float* b_v = (const float*)d_in[8];
    float* Z = (float*)d_out;

    cudaFuncSetAttribute(proj_all_kernel<0>, cudaFuncAttributeMaxDynamicSharedMemorySize, SMEM_BYTES);
    cudaFuncSetAttribute(proj_all_kernel<1>, cudaFuncAttributeMaxDynamicSharedMemorySize, SMEM_BYTES);
    cudaFuncSetAttribute(bm_split_kernel, cudaFuncAttributeMaxDynamicSharedMemorySize, SMEM_BYTES);
    cudaFuncSetAttribute(z_gemm_kernel, cudaFuncAttributeMaxDynamicSharedMemorySize, SMEM_BYTES);

    // side stream + events (created per call, not destroyed: destroying with
    // capture-pending work would invalidate graph capture).
    cudaStream_t s2;
    cudaStreamCreate(&s2);
    cudaEvent_t evW, evKV, evS;
    cudaEventCreateWithFlags(&evW, cudaEventDisableTiming);
    cudaEventCreateWithFlags(&evKV, cudaEventDisableTiming);
    cudaEventCreateWithFlags(&evS, cudaEventDisableTiming);

    // main: weights, fork point
    wt_kernel<<<dim3(16, 16, 3), dim3(32, 8)>>>(W_q, W_k, W_v);
    cudaEventRecord(evW, 0);

    // main: projKV -> bm_split
    proj_all_kernel<1><<<dim3(4, 256, 2), 256, SMEM_BYTES>>>(
        x_q, x_k, x_v, b_q, b_k, b_v);
    cudaEventRecord(evKV, 0);
    bm_split_kernel<<<dim3(4, 8, 8), 256, SMEM_BYTES>>>();

    // side: projQ -> (after projKV) combine_sums
    cudaStreamWaitEvent(s2, evW, 0);
    proj_all_kernel<0><<<dim3(4, 256, 1), 256, SMEM_BYTES, s2>>>(
        x_q, x_k, x_v, b_q, b_k, b_v);
    cudaStreamWaitEvent(s2, evKV, 0);
    combine_sums_kernel<<<8, 512, 0, s2>>>();
    cudaEventRecord(evS, s2);

    // join: bm_combine needs sums + bm partials
    cudaStreamWaitEvent(0, evS, 0);
    bm_combine_kernel<<<2048, 256>>>();
    z_gemm_kernel<<<dim3(4, 32, 8), 256, SMEM_BYTES>>>(Z);
}